// round 1
// baseline (speedup 1.0000x reference)
#include <cuda_runtime.h>
#include <math.h>

// ---------------- problem constants ----------------
#define BB    4
#define SS    1024
#define TT    4096          // B*S tokens
#define DD    768
#define HH    12
#define DHH   64
#define NOPE_ 32
#define ROPE_ 32
#define QP_   384
#define KVP_  512
#define KVW_  544           // KVP + ROPE
#define UKV_  1152          // D + H*NOPE
#define EE    8
#define FF_   3072

// ---------------- scratch (static device globals; no allocation) ----------------
__device__ float g_h1[TT * DD];
__device__ float g_cq[TT * QP_];
__device__ float g_q[TT * DD];
__device__ float g_ckv[TT * KVW_];
__device__ float g_kvl[TT * KVP_];
__device__ float g_kvu[TT * UKV_];
__device__ float g_kr[TT * ROPE_];
__device__ float g_ao[TT * DD];
__device__ float g_x2[TT * DD];
__device__ float g_h2[TT * DD];
__device__ float g_sh[TT * DD];
__device__ float g_hid[TT * FF_];           // shared-expert hidden (reused)
__device__ float g_ehid[2 * TT * FF_];      // routed hidden, compact (exactly 2*T rows total)
__device__ float g_slots[2 * TT * DD];      // routed output per top-k slot
__device__ int   g_tope[TT * 2];
__device__ float g_topg[TT * 2];
__device__ int   g_eidx[EE * TT];
__device__ float g_egate[EE * TT];
__device__ int   g_eslot[EE * TT];
__device__ int   g_cnt[EE];
__device__ int   g_off[EE];

// ---------------- LayerNorm ----------------
__global__ void __launch_bounds__(256) ln_kernel(
    const float* __restrict__ in, int istride, int width,
    float* __restrict__ out, int ostride,
    const float* __restrict__ w, const float* __restrict__ b)
{
    __shared__ float rowc[768];
    __shared__ float red[256];
    int r = blockIdx.x, tid = threadIdx.x;
    const float* ip = in + (size_t)r * istride;
    float s = 0.f;
    for (int i = tid; i < width; i += 256) { float v = ip[i]; rowc[i] = v; s += v; }
    red[tid] = s; __syncthreads();
    for (int st = 128; st > 0; st >>= 1) { if (tid < st) red[tid] += red[tid + st]; __syncthreads(); }
    float mean = red[0] / (float)width;
    __syncthreads();
    float s2 = 0.f;
    for (int i = tid; i < width; i += 256) { float d = rowc[i] - mean; s2 += d * d; }
    red[tid] = s2; __syncthreads();
    for (int st = 128; st > 0; st >>= 1) { if (tid < st) red[tid] += red[tid + st]; __syncthreads(); }
    float inv = rsqrtf(red[0] / (float)width + 1e-5f);
    float* op = out + (size_t)r * ostride;
    for (int i = tid; i < width; i += 256) {
        float v = (rowc[i] - mean) * inv * w[i];
        if (b) v += b[i];
        op[i] = v;
    }
}

// ---------------- generic tiled SGEMM  C[M,N] = A[M,K] * B ----------------
// BT=0: B is [K,N] row-major.  BT=1: B is [N,K] row-major (i.e. C = A * B^T).
// amode: 0 arow=m; 1 arow=tokList[base+m]; 2 arow=off[e]+m
// cmode: 0 crow=m; 1 crow=off[e]+m; 2 crow=slot*TT+tok, scaled by gate
template<int BT>
__global__ void __launch_bounds__(256) gemm_kernel(
    const float* __restrict__ A, int lda,
    const float* __restrict__ B, int ldb,
    float* __restrict__ C, int ldc,
    int M, int N, int K,
    int doGelu,
    const float* __restrict__ addC,
    const int* __restrict__ tokList, const float* __restrict__ gateList,
    const int* __restrict__ slotList, int listBase,
    const int* __restrict__ offArr, const int* __restrict__ cntArr, int eIdx,
    int amode, int cmode)
{
    int Mreal = cntArr ? cntArr[eIdx] : M;
    int mt = blockIdx.y * 64, nt = blockIdx.x * 64;
    if (mt >= Mreal) return;
    int offv = offArr ? offArr[eIdx] : 0;
    __shared__ float As[16][64];
    __shared__ float Bs[16][64];
    int tid = threadIdx.x;
    int ty = tid >> 4, tx = tid & 15;
    float acc[4][4];
#pragma unroll
    for (int i = 0; i < 4; i++)
#pragma unroll
        for (int j = 0; j < 4; j++) acc[i][j] = 0.f;

    for (int k0 = 0; k0 < K; k0 += 16) {
        // load A tile (gathered)
#pragma unroll
        for (int i = 0; i < 4; i++) {
            int e = tid + i * 256;
            int m = e >> 4, k = e & 15;
            int gm = mt + m;
            float v = 0.f;
            if (gm < Mreal) {
                int arow;
                if (amode == 0) arow = gm;
                else if (amode == 1) arow = tokList[listBase + gm];
                else arow = offv + gm;
                v = A[(size_t)arow * lda + k0 + k];
            }
            As[k][m] = v;
        }
        // load B tile
        if (BT == 0) {
#pragma unroll
            for (int i = 0; i < 4; i++) {
                int e = tid + i * 256;
                int k = e >> 6, n = e & 63;
                int gn = nt + n;
                Bs[k][n] = (gn < N) ? B[(size_t)(k0 + k) * ldb + gn] : 0.f;
            }
        } else {
#pragma unroll
            for (int i = 0; i < 4; i++) {
                int e = tid + i * 256;
                int n = e >> 4, k = e & 15;
                int gn = nt + n;
                Bs[k][n] = (gn < N) ? B[(size_t)gn * ldb + k0 + k] : 0.f;
            }
        }
        __syncthreads();
#pragma unroll
        for (int k = 0; k < 16; k++) {
            float4 av = *reinterpret_cast<const float4*>(&As[k][ty * 4]);
            float4 bv = *reinterpret_cast<const float4*>(&Bs[k][tx * 4]);
            float a0[4] = {av.x, av.y, av.z, av.w};
            float b0[4] = {bv.x, bv.y, bv.z, bv.w};
#pragma unroll
            for (int i = 0; i < 4; i++)
#pragma unroll
                for (int j = 0; j < 4; j++)
                    acc[i][j] += a0[i] * b0[j];
        }
        __syncthreads();
    }

#pragma unroll
    for (int i = 0; i < 4; i++) {
        int gm = mt + ty * 4 + i;
        if (gm >= Mreal) continue;
        int crow; float scale = 1.f;
        if (cmode == 0) crow = gm;
        else if (cmode == 1) crow = offv + gm;
        else {
            crow = slotList[listBase + gm] * TT + tokList[listBase + gm];
            scale = gateList[listBase + gm];
        }
#pragma unroll
        for (int j = 0; j < 4; j++) {
            int gn = nt + tx * 4 + j;
            if (gn >= N) continue;
            float v = acc[i][j];
            if (doGelu) v = 0.5f * v * (1.f + erff(v * 0.70710678118654752f));
            v *= scale;
            if (addC) v += addC[(size_t)crow * ldc + gn];
            C[(size_t)crow * ldc + gn] = v;
        }
    }
}

// ---------------- RoPE ----------------
__global__ void rope_q_kernel(float* __restrict__ q)
{
    int idx = blockIdx.x * blockDim.x + threadIdx.x;   // T*H*16
    if (idx >= TT * HH * 16) return;
    int j = idx & 15;
    int h = (idx >> 4) % HH;
    int t = idx / (HH * 16);
    int s = t & (SS - 1);
    float f = powf(10000.f, -(float)j / 32.f);
    float a = (float)s * f;
    float c = cosf(a), sn = sinf(a);
    size_t base = (size_t)t * DD + h * DHH + NOPE_;
    float x1 = q[base + j];
    float x2 = q[base + 16 + j];
    q[base + j]      = x1 * c - x2 * sn;
    q[base + 16 + j] = x2 * c + x1 * sn;
}

__global__ void rope_k_kernel(const float* __restrict__ ckv, float* __restrict__ kr)
{
    int idx = blockIdx.x * blockDim.x + threadIdx.x;   // T*16
    if (idx >= TT * 16) return;
    int j = idx & 15;
    int t = idx >> 4;
    int s = t & (SS - 1);
    float f = powf(10000.f, -(float)j / 32.f);
    float a = (float)s * f;
    float c = cosf(a), sn = sinf(a);
    size_t base = (size_t)t * KVW_ + KVP_;
    float x1 = ckv[base + j];
    float x2 = ckv[base + 16 + j];
    kr[(size_t)t * ROPE_ + j]      = x1 * c - x2 * sn;
    kr[(size_t)t * ROPE_ + 16 + j] = x2 * c + x1 * sn;
}

// ---------------- causal flash attention (fp32) ----------------
__global__ void __launch_bounds__(64) attn_kernel(
    const float* __restrict__ Q, const float* __restrict__ kvu,
    const float* __restrict__ kr, float* __restrict__ O)
{
    int qt = blockIdx.x, h = blockIdx.y, b = blockIdx.z;
    int row = threadIdx.x;
    int qi = qt * 64 + row;
    int t0q = b * SS + qt * 64;
    __shared__ float qs[64][65];
    __shared__ float ks[32][65];
    __shared__ float vs[32][65];

    for (int r = 0; r < 64; r++)
        qs[r][row] = Q[(size_t)(t0q + r) * DD + h * DHH + row];
    __syncthreads();

    float acc[64];
#pragma unroll
    for (int d = 0; d < 64; d++) acc[d] = 0.f;
    float mcur = -3.0e38f, l = 0.f;

    int ntiles = 2 * qt + 2;  // tiles of 32 keys covering [0, qt*64+63]
    for (int kt = 0; kt < ntiles; kt++) {
        int kb = kt * 32;
        for (int z = 0; z < 32; z++) {
            int kg = b * SS + kb + z;
            if (row < 32) ks[z][row] = kvu[(size_t)kg * UKV_ + h * 96 + row];
            else          ks[z][row] = kr[(size_t)kg * ROPE_ + (row - 32)];
            vs[z][row] = kvu[(size_t)kg * UKV_ + h * 96 + 32 + row];
        }
        __syncthreads();
        int jmax = qi - kb; if (jmax > 31) jmax = 31;
        for (int j = 0; j <= jmax; j++) {
            float s = 0.f;
#pragma unroll
            for (int d = 0; d < 64; d++) s += qs[row][d] * ks[j][d];
            s *= 0.125f;
            float mnew = fmaxf(mcur, s);
            float corr = expf(mcur - mnew);
            float p = expf(s - mnew);
            l = l * corr + p;
#pragma unroll
            for (int d = 0; d < 64; d++) acc[d] = acc[d] * corr + p * vs[j][d];
            mcur = mnew;
        }
        __syncthreads();
    }
    float invl = 1.f / l;
    float* op = O + (size_t)(b * SS + qi) * DD + h * DHH;
#pragma unroll
    for (int d = 0; d < 64; d++) op[d] = acc[d] * invl;
}

// ---------------- routing ----------------
__global__ void route_kernel(const float* __restrict__ h2,
                             const float* __restrict__ cent,
                             const float* __restrict__ bias,
                             int* __restrict__ tope, float* __restrict__ topg)
{
    int warp = (blockIdx.x * blockDim.x + threadIdx.x) >> 5;
    int lane = threadIdx.x & 31;
    if (warp >= TT) return;
    const float* hp = h2 + (size_t)warp * DD;
    float raw[EE];
    for (int e = 0; e < EE; e++) {
        const float* cp = cent + (size_t)e * DD;
        float p = 0.f;
        for (int d = lane; d < DD; d += 32) p += hp[d] * cp[d];
#pragma unroll
        for (int o = 16; o > 0; o >>= 1) p += __shfl_xor_sync(0xffffffff, p, o);
        raw[e] = p;
    }
    if (lane == 0) {
        int i0 = 0, i1 = -1;
        float b0 = -3.4e38f, b1 = -3.4e38f;
        for (int e = 0; e < EE; e++) { float v = raw[e] + bias[e]; if (v > b0) { b0 = v; i0 = e; } }
        for (int e = 0; e < EE; e++) { if (e == i0) continue; float v = raw[e] + bias[e]; if (v > b1) { b1 = v; i1 = e; } }
        float g0 = 1.f / (1.f + expf(-raw[i0]));
        float g1 = 1.f / (1.f + expf(-raw[i1]));
        float sg = g0 + g1 + 1e-9f;
        tope[warp * 2] = i0; tope[warp * 2 + 1] = i1;
        topg[warp * 2] = g0 / sg; topg[warp * 2 + 1] = g1 / sg;
    }
}

// ---------------- deterministic per-expert list build ----------------
__global__ void build_lists_kernel(const int* __restrict__ tope, const float* __restrict__ topg,
                                   int* __restrict__ eidx, float* __restrict__ egate,
                                   int* __restrict__ eslot, int* __restrict__ cnt)
{
    int e = blockIdx.x;
    int tid = threadIdx.x;  // 256 threads, 16 tokens each
    __shared__ int c[256];
    int t0 = tid * 16;
    int lc = 0;
    for (int i = 0; i < 16; i++) {
        int t = t0 + i;
        lc += (tope[t * 2] == e) || (tope[t * 2 + 1] == e);
    }
    c[tid] = lc; __syncthreads();
    if (tid == 0) {
        int tot = 0;
        for (int i = 0; i < 256; i++) { int v = c[i]; c[i] = tot; tot += v; }
        cnt[e] = tot;
    }
    __syncthreads();
    int pos = c[tid];
    for (int i = 0; i < 16; i++) {
        int t = t0 + i;
        int slot = -1;
        if (tope[t * 2] == e) slot = 0;
        else if (tope[t * 2 + 1] == e) slot = 1;
        if (slot >= 0) {
            int p = e * TT + pos;
            eidx[p] = t;
            egate[p] = topg[t * 2 + slot];
            eslot[p] = slot;
            pos++;
        }
    }
}

__global__ void offsets_kernel(const int* __restrict__ cnt, int* __restrict__ off)
{
    if (threadIdx.x == 0) {
        int a = 0;
        for (int e = 0; e < EE; e++) { off[e] = a; a += cnt[e]; }
    }
}

// ---------------- final combine ----------------
__global__ void combine_kernel(const float* __restrict__ x2, const float* __restrict__ sh,
                               const float* __restrict__ slots, float* __restrict__ out)
{
    int i = blockIdx.x * 256 + threadIdx.x;
    if (i < TT * DD)
        out[i] = x2[i] + sh[i] + slots[i] + slots[TT * DD + i];
}

// ---------------- host launcher ----------------
static void launch_gemm(bool bt,
                        const float* A, int lda, const float* B, int ldb,
                        float* C, int ldc, int M, int N, int K,
                        bool gelu, const float* addC,
                        const int* tok, const float* gate, const int* slot, int listBase,
                        const int* offA, const int* cntA, int e,
                        int amode, int cmode)
{
    dim3 grid((N + 63) / 64, (M + 63) / 64);
    if (bt)
        gemm_kernel<1><<<grid, 256>>>(A, lda, B, ldb, C, ldc, M, N, K,
                                      gelu ? 1 : 0, addC, tok, gate, slot, listBase,
                                      offA, cntA, e, amode, cmode);
    else
        gemm_kernel<0><<<grid, 256>>>(A, lda, B, ldb, C, ldc, M, N, K,
                                      gelu ? 1 : 0, addC, tok, gate, slot, listBase,
                                      offA, cntA, e, amode, cmode);
}

extern "C" void kernel_launch(void* const* d_in, const int* in_sizes, int n_in,
                              void* d_out, int out_size)
{
    const float* x       = (const float*)d_in[0];
    const float* ln1_w   = (const float*)d_in[1];
    const float* ln2_w   = (const float*)d_in[2];
    const float* W_dq    = (const float*)d_in[3];
    const float* W_uq    = (const float*)d_in[4];
    const float* q_ln_w  = (const float*)d_in[5];
    const float* q_ln_b  = (const float*)d_in[6];
    const float* W_dkv   = (const float*)d_in[7];
    const float* W_ukv   = (const float*)d_in[8];
    const float* kv_ln_w = (const float*)d_in[9];
    const float* kv_ln_b = (const float*)d_in[10];
    const float* W_o     = (const float*)d_in[11];
    const float* s_fc    = (const float*)d_in[12];
    const float* s_proj  = (const float*)d_in[13];
    const float* e_fc    = (const float*)d_in[14];
    const float* e_proj  = (const float*)d_in[15];
    const float* cent    = (const float*)d_in[16];
    const float* rbias   = (const float*)d_in[17];
    float* out = (float*)d_out;

    float *h1, *cq, *q, *ckv, *kvl, *kvu, *kr, *ao, *x2, *h2, *sh, *hid, *ehid, *slots, *egate, *topg;
    int *eidx, *eslot, *cnt, *off, *tope;
    cudaGetSymbolAddress((void**)&h1, g_h1);
    cudaGetSymbolAddress((void**)&cq, g_cq);
    cudaGetSymbolAddress((void**)&q, g_q);
    cudaGetSymbolAddress((void**)&ckv, g_ckv);
    cudaGetSymbolAddress((void**)&kvl, g_kvl);
    cudaGetSymbolAddress((void**)&kvu, g_kvu);
    cudaGetSymbolAddress((void**)&kr, g_kr);
    cudaGetSymbolAddress((void**)&ao, g_ao);
    cudaGetSymbolAddress((void**)&x2, g_x2);
    cudaGetSymbolAddress((void**)&h2, g_h2);
    cudaGetSymbolAddress((void**)&sh, g_sh);
    cudaGetSymbolAddress((void**)&hid, g_hid);
    cudaGetSymbolAddress((void**)&ehid, g_ehid);
    cudaGetSymbolAddress((void**)&slots, g_slots);
    cudaGetSymbolAddress((void**)&egate, g_egate);
    cudaGetSymbolAddress((void**)&topg, g_topg);
    cudaGetSymbolAddress((void**)&eidx, g_eidx);
    cudaGetSymbolAddress((void**)&eslot, g_eslot);
    cudaGetSymbolAddress((void**)&cnt, g_cnt);
    cudaGetSymbolAddress((void**)&off, g_off);
    cudaGetSymbolAddress((void**)&tope, g_tope);

    // 1. h1 = LN(x) * ln1_w
    ln_kernel<<<TT, 256>>>(x, DD, DD, h1, DD, ln1_w, nullptr);
    // 2. cq_raw = h1 @ W_dq ; LN in place
    launch_gemm(false, h1, DD, W_dq, QP_, cq, QP_, TT, QP_, DD,
                false, nullptr, nullptr, nullptr, nullptr, 0, nullptr, nullptr, 0, 0, 0);
    ln_kernel<<<TT, 256>>>(cq, QP_, QP_, cq, QP_, q_ln_w, q_ln_b);
    // 3. Q = cq @ W_uq
    launch_gemm(false, cq, QP_, W_uq, DD, q, DD, TT, DD, QP_,
                false, nullptr, nullptr, nullptr, nullptr, 0, nullptr, nullptr, 0, 0, 0);
    // 4. ckv = h1 @ W_dkv
    launch_gemm(false, h1, DD, W_dkv, KVW_, ckv, KVW_, TT, KVW_, DD,
                false, nullptr, nullptr, nullptr, nullptr, 0, nullptr, nullptr, 0, 0, 0);
    // 5. kvl = LN(ckv[:, :512])
    ln_kernel<<<TT, 256>>>(ckv, KVW_, KVP_, kvl, KVP_, kv_ln_w, kv_ln_b);
    // 6. kvu = kvl @ W_ukv
    launch_gemm(false, kvl, KVP_, W_ukv, UKV_, kvu, UKV_, TT, UKV_, KVP_,
                false, nullptr, nullptr, nullptr, nullptr, 0, nullptr, nullptr, 0, 0, 0);
    // 7. RoPE
    rope_q_kernel<<<(TT * HH * 16 + 255) / 256, 256>>>(q);
    rope_k_kernel<<<(TT * 16 + 255) / 256, 256>>>(ckv, kr);
    // 8. attention
    {
        dim3 agrid(SS / 64, HH, BB);
        attn_kernel<<<agrid, 64>>>(q, kvu, kr, ao);
    }
    // 9. x2 = x + ao @ W_o^T
    launch_gemm(true, ao, DD, W_o, DD, x2, DD, TT, DD, DD,
                false, x, nullptr, nullptr, nullptr, 0, nullptr, nullptr, 0, 0, 0);
    // 10. h2 = LN(x2) * ln2_w
    ln_kernel<<<TT, 256>>>(x2, DD, DD, h2, DD, ln2_w, nullptr);
    // 11. shared experts
    for (int n = 0; n < 2; n++) {
        launch_gemm(true, h2, DD, s_fc + (size_t)n * FF_ * DD, DD, hid, FF_, TT, FF_, DD,
                    true, nullptr, nullptr, nullptr, nullptr, 0, nullptr, nullptr, 0, 0, 0);
        launch_gemm(true, hid, FF_, s_proj + (size_t)n * DD * FF_, FF_, sh, DD, TT, DD, FF_,
                    false, n == 0 ? nullptr : sh,
                    nullptr, nullptr, nullptr, 0, nullptr, nullptr, 0, 0, 0);
    }
    // 12. routing + lists
    route_kernel<<<TT / 4, 128>>>(h2, cent, rbias, tope, topg);
    build_lists_kernel<<<EE, 256>>>(tope, topg, eidx, egate, eslot, cnt);
    offsets_kernel<<<1, 32>>>(cnt, off);
    // 13. routed experts (gathered, deterministic slot scatter)
    for (int e = 0; e < EE; e++) {
        launch_gemm(true, h2, DD, e_fc + (size_t)e * FF_ * DD, DD, ehid, FF_, TT, FF_, DD,
                    true, nullptr, eidx, egate, eslot, e * TT, off, cnt, e, 1, 1);
    }
    for (int e = 0; e < EE; e++) {
        launch_gemm(true, ehid, FF_, e_proj + (size_t)e * DD * FF_, FF_, slots, DD, TT, DD, FF_,
                    false, nullptr, eidx, egate, eslot, e * TT, off, cnt, e, 2, 2);
    }
    // 14. out = x2 + shared + routed
    combine_kernel<<<(TT * DD + 255) / 256, 256>>>(x2, sh, slots, out);
}

// round 2
// speedup vs baseline: 2.9352x; 2.9352x over previous
#include <cuda_runtime.h>
#include <math.h>

// ---------------- problem constants ----------------
#define BB    4
#define SS    1024
#define TT    4096          // B*S tokens
#define DD    768
#define HH    12
#define DHH   64
#define NOPE_ 32
#define ROPE_ 32
#define QP_   384
#define KVP_  512
#define KVW_  544           // KVP + ROPE
#define UKV_  1152          // D + H*NOPE
#define EE    8
#define FF_   3072

// ---------------- scratch (static device globals; no allocation) ----------------
__device__ float g_h1[TT * DD];
__device__ float g_cq[TT * QP_];
__device__ float g_q[TT * DD];
__device__ float g_ckv[TT * KVW_];
__device__ float g_kvl[TT * KVP_];
__device__ float g_kvu[TT * UKV_];
__device__ float g_kr[TT * ROPE_];
__device__ float g_ao[TT * DD];
__device__ float g_x2[TT * DD];
__device__ float g_h2[TT * DD];
__device__ float g_sh[TT * DD];
__device__ float g_hid[TT * FF_];           // shared-expert hidden (reused)
__device__ float g_ehid[2 * TT * FF_];      // routed hidden, compact
__device__ float g_slots[2 * TT * DD];      // routed output per top-k slot
__device__ int   g_tope[TT * 2];
__device__ float g_topg[TT * 2];
__device__ int   g_eidx[EE * TT];
__device__ float g_egate[EE * TT];
__device__ int   g_eslot[EE * TT];
__device__ int   g_cnt[EE];
__device__ int   g_off[EE];

// ---------------- LayerNorm ----------------
__global__ void __launch_bounds__(256) ln_kernel(
    const float* __restrict__ in, int istride, int width,
    float* __restrict__ out, int ostride,
    const float* __restrict__ w, const float* __restrict__ b)
{
    __shared__ float rowc[768];
    __shared__ float red[256];
    int r = blockIdx.x, tid = threadIdx.x;
    const float* ip = in + (size_t)r * istride;
    float s = 0.f;
    for (int i = tid; i < width; i += 256) { float v = ip[i]; rowc[i] = v; s += v; }
    red[tid] = s; __syncthreads();
    for (int st = 128; st > 0; st >>= 1) { if (tid < st) red[tid] += red[tid + st]; __syncthreads(); }
    float mean = red[0] / (float)width;
    __syncthreads();
    float s2 = 0.f;
    for (int i = tid; i < width; i += 256) { float d = rowc[i] - mean; s2 += d * d; }
    red[tid] = s2; __syncthreads();
    for (int st = 128; st > 0; st >>= 1) { if (tid < st) red[tid] += red[tid + st]; __syncthreads(); }
    float inv = rsqrtf(red[0] / (float)width + 1e-5f);
    float* op = out + (size_t)r * ostride;
    for (int i = tid; i < width; i += 256) {
        float v = (rowc[i] - mean) * inv * w[i];
        if (b) v += b[i];
        op[i] = v;
    }
}

// ---------------- TF32 tensor-core GEMM ----------------
// C[M,N] = A[M,K] * B    (BT=0: B is [K,N]; BT=1: B is [N,K] i.e. C = A*B^T)
// amode: 0 arow=m; 1 arow=tokList[base+m]; 2 arow=off[e]+m
// cmode: 0 crow=m; 1 crow=off[e]+m; 2 crow=slot*TT+tok, scaled by gate
// Tiles: 128x64x32, 256 threads (8 warps), warp = 32x32, mma m16n8k8.

#define SK 36   // smem k-stride (conflict-free fragment loads)

__device__ __forceinline__ unsigned f2tf32(float v) {
    unsigned u;
    asm("cvt.rna.tf32.f32 %0, %1;" : "=r"(u) : "f"(v));
    return u;
}

__device__ __forceinline__ void mma_tf32(float* c, const unsigned* a, const unsigned* b) {
    asm volatile("mma.sync.aligned.m16n8k8.row.col.f32.tf32.tf32.f32 "
                 "{%0,%1,%2,%3}, {%4,%5,%6,%7}, {%8,%9}, {%0,%1,%2,%3};"
                 : "+f"(c[0]), "+f"(c[1]), "+f"(c[2]), "+f"(c[3])
                 : "r"(a[0]), "r"(a[1]), "r"(a[2]), "r"(a[3]),
                   "r"(b[0]), "r"(b[1]));
}

template<int BT>
__global__ void __launch_bounds__(256) gemm_kernel(
    const float* __restrict__ A, int lda,
    const float* __restrict__ B, int ldb,
    float* __restrict__ C, int ldc,
    int M, int N, int K,
    int doGelu,
    const float* __restrict__ addC,
    const int* __restrict__ tokList, const float* __restrict__ gateList,
    const int* __restrict__ slotList, int listBase,
    const int* __restrict__ offArr, const int* __restrict__ cntArr, int eIdx,
    int amode, int cmode)
{
    int Mreal = cntArr ? cntArr[eIdx] : M;
    int mt = blockIdx.y * 128, nt = blockIdx.x * 64;
    if (mt >= Mreal) return;
    int offv = offArr ? offArr[eIdx] : 0;

    __shared__ unsigned As[128][SK];   // [m][k]
    __shared__ unsigned Bs[64][SK];    // [n][k]

    int tid = threadIdx.x;
    int wid = tid >> 5, lane = tid & 31;
    int wm = wid & 3, wn = wid >> 2;         // warp tile: rows wm*32, cols wn*32
    int lrow = lane >> 2;                     // 0..7
    int lcol = lane & 3;                      // 0..3

    float acc[2][4][4];
#pragma unroll
    for (int i = 0; i < 2; i++)
#pragma unroll
        for (int j = 0; j < 4; j++)
#pragma unroll
            for (int r = 0; r < 4; r++) acc[i][j][r] = 0.f;

    // precompute gathered A rows for this block's 4 fill rows
    int fr = tid >> 3, ff = tid & 7;          // fr:0..31 row, ff:0..7 float4 col

    for (int k0 = 0; k0 < K; k0 += 32) {
        // ---- fill A tile: 128 x 32 ----
#pragma unroll
        for (int i = 0; i < 4; i++) {
            int m = fr + i * 32;
            int gm = mt + m;
            float4 v = make_float4(0.f, 0.f, 0.f, 0.f);
            if (gm < Mreal) {
                int arow;
                if (amode == 0) arow = gm;
                else if (amode == 1) arow = tokList[listBase + gm];
                else arow = offv + gm;
                v = *reinterpret_cast<const float4*>(A + (size_t)arow * lda + k0 + ff * 4);
            }
            unsigned* dst = &As[m][ff * 4];
            dst[0] = f2tf32(v.x); dst[1] = f2tf32(v.y);
            dst[2] = f2tf32(v.z); dst[3] = f2tf32(v.w);
        }
        // ---- fill B tile: 64 x 32 ----
        if (BT == 1) {
#pragma unroll
            for (int i = 0; i < 2; i++) {
                int n = fr + i * 32;
                int gn = nt + n;
                float4 v = make_float4(0.f, 0.f, 0.f, 0.f);
                if (gn < N)
                    v = *reinterpret_cast<const float4*>(B + (size_t)gn * ldb + k0 + ff * 4);
                unsigned* dst = &Bs[n][ff * 4];
                dst[0] = f2tf32(v.x); dst[1] = f2tf32(v.y);
                dst[2] = f2tf32(v.z); dst[3] = f2tf32(v.w);
            }
        } else {
            int n = tid & 63, kq = tid >> 6;   // n:0..63, kq:0..3
            int gn = nt + n;
#pragma unroll
            for (int i = 0; i < 8; i++) {
                int k = kq + i * 4;
                float v = (gn < N) ? B[(size_t)(k0 + k) * ldb + gn] : 0.f;
                Bs[n][k] = f2tf32(v);
            }
        }
        __syncthreads();

        // ---- compute 4 k-steps of 8 ----
#pragma unroll
        for (int ks = 0; ks < 4; ks++) {
            int kb = ks * 8;
            unsigned afr[2][4];
#pragma unroll
            for (int m2 = 0; m2 < 2; m2++) {
                int r0 = wm * 32 + m2 * 16 + lrow;
                afr[m2][0] = As[r0][kb + lcol];
                afr[m2][1] = As[r0 + 8][kb + lcol];
                afr[m2][2] = As[r0][kb + 4 + lcol];
                afr[m2][3] = As[r0 + 8][kb + 4 + lcol];
            }
            unsigned bfr[4][2];
#pragma unroll
            for (int n2 = 0; n2 < 4; n2++) {
                int nn = wn * 32 + n2 * 8 + lrow;
                bfr[n2][0] = Bs[nn][kb + lcol];
                bfr[n2][1] = Bs[nn][kb + 4 + lcol];
            }
#pragma unroll
            for (int m2 = 0; m2 < 2; m2++)
#pragma unroll
                for (int n2 = 0; n2 < 4; n2++)
                    mma_tf32(acc[m2][n2], afr[m2], bfr[n2]);
        }
        __syncthreads();
    }

    // ---- epilogue ----
#pragma unroll
    for (int m2 = 0; m2 < 2; m2++) {
#pragma unroll
        for (int ri = 0; ri < 2; ri++) {          // row half (c0/c1 vs c2/c3)
            int gm = mt + wm * 32 + m2 * 16 + lrow + ri * 8;
            if (gm >= Mreal) continue;
            int crow; float scale = 1.f;
            if (cmode == 0) crow = gm;
            else if (cmode == 1) crow = offv + gm;
            else {
                crow = slotList[listBase + gm] * TT + tokList[listBase + gm];
                scale = gateList[listBase + gm];
            }
#pragma unroll
            for (int n2 = 0; n2 < 4; n2++) {
#pragma unroll
                for (int cj = 0; cj < 2; cj++) {
                    int gn = nt + wn * 32 + n2 * 8 + lcol * 2 + cj;
                    if (gn >= N) continue;
                    float v = acc[m2][n2][ri * 2 + cj];
                    if (doGelu) v = 0.5f * v * (1.f + erff(v * 0.70710678118654752f));
                    v *= scale;
                    if (addC) v += addC[(size_t)crow * ldc + gn];
                    C[(size_t)crow * ldc + gn] = v;
                }
            }
        }
    }
}

// ---------------- RoPE ----------------
__global__ void rope_q_kernel(float* __restrict__ q)
{
    int idx = blockIdx.x * blockDim.x + threadIdx.x;   // T*H*16
    if (idx >= TT * HH * 16) return;
    int j = idx & 15;
    int h = (idx >> 4) % HH;
    int t = idx / (HH * 16);
    int s = t & (SS - 1);
    float f = powf(10000.f, -(float)j / 32.f);
    float a = (float)s * f;
    float c = cosf(a), sn = sinf(a);
    size_t base = (size_t)t * DD + h * DHH + NOPE_;
    float x1 = q[base + j];
    float x2 = q[base + 16 + j];
    q[base + j]      = x1 * c - x2 * sn;
    q[base + 16 + j] = x2 * c + x1 * sn;
}

__global__ void rope_k_kernel(const float* __restrict__ ckv, float* __restrict__ kr)
{
    int idx = blockIdx.x * blockDim.x + threadIdx.x;   // T*16
    if (idx >= TT * 16) return;
    int j = idx & 15;
    int t = idx >> 4;
    int s = t & (SS - 1);
    float f = powf(10000.f, -(float)j / 32.f);
    float a = (float)s * f;
    float c = cosf(a), sn = sinf(a);
    size_t base = (size_t)t * KVW_ + KVP_;
    float x1 = ckv[base + j];
    float x2 = ckv[base + 16 + j];
    kr[(size_t)t * ROPE_ + j]      = x1 * c - x2 * sn;
    kr[(size_t)t * ROPE_ + 16 + j] = x2 * c + x1 * sn;
}

// ---------------- causal flash attention (fp32) ----------------
__global__ void __launch_bounds__(64) attn_kernel(
    const float* __restrict__ Q, const float* __restrict__ kvu,
    const float* __restrict__ kr, float* __restrict__ O)
{
    int qt = blockIdx.x, h = blockIdx.y, b = blockIdx.z;
    int row = threadIdx.x;
    int qi = qt * 64 + row;
    int t0q = b * SS + qt * 64;
    __shared__ float qs[64][65];
    __shared__ float ks[32][65];
    __shared__ float vs[32][65];

    for (int r = 0; r < 64; r++)
        qs[r][row] = Q[(size_t)(t0q + r) * DD + h * DHH + row];
    __syncthreads();

    float acc[64];
#pragma unroll
    for (int d = 0; d < 64; d++) acc[d] = 0.f;
    float mcur = -3.0e38f, l = 0.f;

    int ntiles = 2 * qt + 2;
    for (int kt = 0; kt < ntiles; kt++) {
        int kb = kt * 32;
        for (int z = 0; z < 32; z++) {
            int kg = b * SS + kb + z;
            if (row < 32) ks[z][row] = kvu[(size_t)kg * UKV_ + h * 96 + row];
            else          ks[z][row] = kr[(size_t)kg * ROPE_ + (row - 32)];
            vs[z][row] = kvu[(size_t)kg * UKV_ + h * 96 + 32 + row];
        }
        __syncthreads();
        int jmax = qi - kb; if (jmax > 31) jmax = 31;
        for (int j = 0; j <= jmax; j++) {
            float s = 0.f;
#pragma unroll
            for (int d = 0; d < 64; d++) s += qs[row][d] * ks[j][d];
            s *= 0.125f;
            float mnew = fmaxf(mcur, s);
            float corr = expf(mcur - mnew);
            float p = expf(s - mnew);
            l = l * corr + p;
#pragma unroll
            for (int d = 0; d < 64; d++) acc[d] = acc[d] * corr + p * vs[j][d];
            mcur = mnew;
        }
        __syncthreads();
    }
    float invl = 1.f / l;
    float* op = O + (size_t)(b * SS + qi) * DD + h * DHH;
#pragma unroll
    for (int d = 0; d < 64; d++) op[d] = acc[d] * invl;
}

// ---------------- routing ----------------
__global__ void route_kernel(const float* __restrict__ h2,
                             const float* __restrict__ cent,
                             const float* __restrict__ bias,
                             int* __restrict__ tope, float* __restrict__ topg)
{
    int warp = (blockIdx.x * blockDim.x + threadIdx.x) >> 5;
    int lane = threadIdx.x & 31;
    if (warp >= TT) return;
    const float* hp = h2 + (size_t)warp * DD;
    float raw[EE];
    for (int e = 0; e < EE; e++) {
        const float* cp = cent + (size_t)e * DD;
        float p = 0.f;
        for (int d = lane; d < DD; d += 32) p += hp[d] * cp[d];
#pragma unroll
        for (int o = 16; o > 0; o >>= 1) p += __shfl_xor_sync(0xffffffff, p, o);
        raw[e] = p;
    }
    if (lane == 0) {
        int i0 = 0, i1 = -1;
        float b0 = -3.4e38f, b1 = -3.4e38f;
        for (int e = 0; e < EE; e++) { float v = raw[e] + bias[e]; if (v > b0) { b0 = v; i0 = e; } }
        for (int e = 0; e < EE; e++) { if (e == i0) continue; float v = raw[e] + bias[e]; if (v > b1) { b1 = v; i1 = e; } }
        float g0 = 1.f / (1.f + expf(-raw[i0]));
        float g1 = 1.f / (1.f + expf(-raw[i1]));
        float sg = g0 + g1 + 1e-9f;
        tope[warp * 2] = i0; tope[warp * 2 + 1] = i1;
        topg[warp * 2] = g0 / sg; topg[warp * 2 + 1] = g1 / sg;
    }
}

// ---------------- deterministic per-expert list build ----------------
__global__ void build_lists_kernel(const int* __restrict__ tope, const float* __restrict__ topg,
                                   int* __restrict__ eidx, float* __restrict__ egate,
                                   int* __restrict__ eslot, int* __restrict__ cnt)
{
    int e = blockIdx.x;
    int tid = threadIdx.x;
    __shared__ int c[256];
    int t0 = tid * 16;
    int lc = 0;
    for (int i = 0; i < 16; i++) {
        int t = t0 + i;
        lc += (tope[t * 2] == e) || (tope[t * 2 + 1] == e);
    }
    c[tid] = lc; __syncthreads();
    if (tid == 0) {
        int tot = 0;
        for (int i = 0; i < 256; i++) { int v = c[i]; c[i] = tot; tot += v; }
        cnt[e] = tot;
    }
    __syncthreads();
    int pos = c[tid];
    for (int i = 0; i < 16; i++) {
        int t = t0 + i;
        int slot = -1;
        if (tope[t * 2] == e) slot = 0;
        else if (tope[t * 2 + 1] == e) slot = 1;
        if (slot >= 0) {
            int p = e * TT + pos;
            eidx[p] = t;
            egate[p] = topg[t * 2 + slot];
            eslot[p] = slot;
            pos++;
        }
    }
}

__global__ void offsets_kernel(const int* __restrict__ cnt, int* __restrict__ off)
{
    if (threadIdx.x == 0) {
        int a = 0;
        for (int e = 0; e < EE; e++) { off[e] = a; a += cnt[e]; }
    }
}

// ---------------- final combine ----------------
__global__ void combine_kernel(const float* __restrict__ x2, const float* __restrict__ sh,
                               const float* __restrict__ slots, float* __restrict__ out)
{
    int i = blockIdx.x * 256 + threadIdx.x;
    if (i < TT * DD)
        out[i] = x2[i] + sh[i] + slots[i] + slots[TT * DD + i];
}

// ---------------- host launcher ----------------
static void launch_gemm(bool bt,
                        const float* A, int lda, const float* B, int ldb,
                        float* C, int ldc, int M, int N, int K,
                        bool gelu, const float* addC,
                        const int* tok, const float* gate, const int* slot, int listBase,
                        const int* offA, const int* cntA, int e,
                        int amode, int cmode)
{
    dim3 grid((N + 63) / 64, (M + 127) / 128);
    if (bt)
        gemm_kernel<1><<<grid, 256>>>(A, lda, B, ldb, C, ldc, M, N, K,
                                      gelu ? 1 : 0, addC, tok, gate, slot, listBase,
                                      offA, cntA, e, amode, cmode);
    else
        gemm_kernel<0><<<grid, 256>>>(A, lda, B, ldb, C, ldc, M, N, K,
                                      gelu ? 1 : 0, addC, tok, gate, slot, listBase,
                                      offA, cntA, e, amode, cmode);
}

extern "C" void kernel_launch(void* const* d_in, const int* in_sizes, int n_in,
                              void* d_out, int out_size)
{
    const float* x       = (const float*)d_in[0];
    const float* ln1_w   = (const float*)d_in[1];
    const float* ln2_w   = (const float*)d_in[2];
    const float* W_dq    = (const float*)d_in[3];
    const float* W_uq    = (const float*)d_in[4];
    const float* q_ln_w  = (const float*)d_in[5];
    const float* q_ln_b  = (const float*)d_in[6];
    const float* W_dkv   = (const float*)d_in[7];
    const float* W_ukv   = (const float*)d_in[8];
    const float* kv_ln_w = (const float*)d_in[9];
    const float* kv_ln_b = (const float*)d_in[10];
    const float* W_o     = (const float*)d_in[11];
    const float* s_fc    = (const float*)d_in[12];
    const float* s_proj  = (const float*)d_in[13];
    const float* e_fc    = (const float*)d_in[14];
    const float* e_proj  = (const float*)d_in[15];
    const float* cent    = (const float*)d_in[16];
    const float* rbias   = (const float*)d_in[17];
    float* out = (float*)d_out;

    float *h1, *cq, *q, *ckv, *kvl, *kvu, *kr, *ao, *x2, *h2, *sh, *hid, *ehid, *slots, *egate, *topg;
    int *eidx, *eslot, *cnt, *off, *tope;
    cudaGetSymbolAddress((void**)&h1, g_h1);
    cudaGetSymbolAddress((void**)&cq, g_cq);
    cudaGetSymbolAddress((void**)&q, g_q);
    cudaGetSymbolAddress((void**)&ckv, g_ckv);
    cudaGetSymbolAddress((void**)&kvl, g_kvl);
    cudaGetSymbolAddress((void**)&kvu, g_kvu);
    cudaGetSymbolAddress((void**)&kr, g_kr);
    cudaGetSymbolAddress((void**)&ao, g_ao);
    cudaGetSymbolAddress((void**)&x2, g_x2);
    cudaGetSymbolAddress((void**)&h2, g_h2);
    cudaGetSymbolAddress((void**)&sh, g_sh);
    cudaGetSymbolAddress((void**)&hid, g_hid);
    cudaGetSymbolAddress((void**)&ehid, g_ehid);
    cudaGetSymbolAddress((void**)&slots, g_slots);
    cudaGetSymbolAddress((void**)&egate, g_egate);
    cudaGetSymbolAddress((void**)&topg, g_topg);
    cudaGetSymbolAddress((void**)&eidx, g_eidx);
    cudaGetSymbolAddress((void**)&eslot, g_eslot);
    cudaGetSymbolAddress((void**)&cnt, g_cnt);
    cudaGetSymbolAddress((void**)&off, g_off);
    cudaGetSymbolAddress((void**)&tope, g_tope);

    // 1. h1 = LN(x)
    ln_kernel<<<TT, 256>>>(x, DD, DD, h1, DD, ln1_w, nullptr);
    // 2. cq = LN(h1 @ W_dq)
    launch_gemm(false, h1, DD, W_dq, QP_, cq, QP_, TT, QP_, DD,
                false, nullptr, nullptr, nullptr, nullptr, 0, nullptr, nullptr, 0, 0, 0);
    ln_kernel<<<TT, 256>>>(cq, QP_, QP_, cq, QP_, q_ln_w, q_ln_b);
    // 3. Q = cq @ W_uq
    launch_gemm(false, cq, QP_, W_uq, DD, q, DD, TT, DD, QP_,
                false, nullptr, nullptr, nullptr, nullptr, 0, nullptr, nullptr, 0, 0, 0);
    // 4. ckv = h1 @ W_dkv
    launch_gemm(false, h1, DD, W_dkv, KVW_, ckv, KVW_, TT, KVW_, DD,
                false, nullptr, nullptr, nullptr, nullptr, 0, nullptr, nullptr, 0, 0, 0);
    // 5. kvl = LN(ckv[:, :512])
    ln_kernel<<<TT, 256>>>(ckv, KVW_, KVP_, kvl, KVP_, kv_ln_w, kv_ln_b);
    // 6. kvu = kvl @ W_ukv
    launch_gemm(false, kvl, KVP_, W_ukv, UKV_, kvu, UKV_, TT, UKV_, KVP_,
                false, nullptr, nullptr, nullptr, nullptr, 0, nullptr, nullptr, 0, 0, 0);
    // 7. RoPE
    rope_q_kernel<<<(TT * HH * 16 + 255) / 256, 256>>>(q);
    rope_k_kernel<<<(TT * 16 + 255) / 256, 256>>>(ckv, kr);
    // 8. attention
    {
        dim3 agrid(SS / 64, HH, BB);
        attn_kernel<<<agrid, 64>>>(q, kvu, kr, ao);
    }
    // 9. x2 = x + ao @ W_o^T
    launch_gemm(true, ao, DD, W_o, DD, x2, DD, TT, DD, DD,
                false, x, nullptr, nullptr, nullptr, 0, nullptr, nullptr, 0, 0, 0);
    // 10. h2 = LN(x2)
    ln_kernel<<<TT, 256>>>(x2, DD, DD, h2, DD, ln2_w, nullptr);
    // 11. shared experts
    for (int n = 0; n < 2; n++) {
        launch_gemm(true, h2, DD, s_fc + (size_t)n * FF_ * DD, DD, hid, FF_, TT, FF_, DD,
                    true, nullptr, nullptr, nullptr, nullptr, 0, nullptr, nullptr, 0, 0, 0);
        launch_gemm(true, hid, FF_, s_proj + (size_t)n * DD * FF_, FF_, sh, DD, TT, DD, FF_,
                    false, n == 0 ? nullptr : sh,
                    nullptr, nullptr, nullptr, 0, nullptr, nullptr, 0, 0, 0);
    }
    // 12. routing + lists
    route_kernel<<<TT / 4, 128>>>(h2, cent, rbias, tope, topg);
    build_lists_kernel<<<EE, 256>>>(tope, topg, eidx, egate, eslot, cnt);
    offsets_kernel<<<1, 32>>>(cnt, off);
    // 13. routed experts
    for (int e = 0; e < EE; e++) {
        launch_gemm(true, h2, DD, e_fc + (size_t)e * FF_ * DD, DD, ehid, FF_, TT, FF_, DD,
                    true, nullptr, eidx, egate, eslot, e * TT, off, cnt, e, 1, 1);
    }
    for (int e = 0; e < EE; e++) {
        launch_gemm(true, ehid, FF_, e_proj + (size_t)e * DD * FF_, FF_, slots, DD, TT, DD, FF_,
                    false, nullptr, eidx, egate, eslot, e * TT, off, cnt, e, 2, 2);
    }
    // 14. out = x2 + shared + routed
    combine_kernel<<<(TT * DD + 255) / 256, 256>>>(x2, sh, slots, out);
}

// round 3
// speedup vs baseline: 3.6271x; 1.2357x over previous
#include <cuda_runtime.h>
#include <math.h>

// ---------------- problem constants ----------------
#define BB    4
#define SS    1024
#define TT    4096
#define DD    768
#define HH    12
#define DHH   64
#define NOPE_ 32
#define ROPE_ 32
#define QP_   384
#define KVP_  512
#define KVW_  544
#define UKV_  1152
#define EE    8
#define FF_   3072

// ---------------- scratch ----------------
__device__ __align__(256) float g_h1[TT * DD];
__device__ __align__(256) float g_cq[TT * QP_];
__device__ __align__(256) float g_q[TT * DD];
__device__ __align__(256) float g_ckv[TT * KVW_];
__device__ __align__(256) float g_kvl[TT * KVP_];
__device__ __align__(256) float g_kvu[TT * UKV_];
__device__ __align__(256) float g_kr[TT * ROPE_];
__device__ __align__(256) float g_ao[TT * DD];
__device__ __align__(256) float g_x2[TT * DD];
__device__ __align__(256) float g_h2[TT * DD];
__device__ __align__(256) float g_sh[TT * DD];
__device__ __align__(256) float g_hid[TT * FF_];
__device__ __align__(256) float g_ehid[2 * TT * FF_];
__device__ __align__(256) float g_slots[2 * TT * DD];
__device__ int   g_tope[TT * 2];
__device__ float g_topg[TT * 2];
__device__ int   g_eidx[EE * TT];
__device__ float g_egate[EE * TT];
__device__ int   g_eslot[EE * TT];
__device__ int   g_cnt[EE];
__device__ int   g_off[EE];

// ---------------- f32x2 packed helpers ----------------
typedef unsigned long long u64t;
__device__ __forceinline__ u64t fma2_(u64t a, u64t b, u64t c) {
    u64t d; asm("fma.rn.f32x2 %0, %1, %2, %3;" : "=l"(d) : "l"(a), "l"(b), "l"(c)); return d;
}
__device__ __forceinline__ u64t mul2_(u64t a, u64t b) {
    u64t d; asm("mul.rn.f32x2 %0, %1, %2;" : "=l"(d) : "l"(a), "l"(b)); return d;
}
__device__ __forceinline__ u64t add2_(u64t a, u64t b) {
    u64t d; asm("add.rn.f32x2 %0, %1, %2;" : "=l"(d) : "l"(a), "l"(b)); return d;
}
__device__ __forceinline__ u64t pack2_(float lo, float hi) {
    u64t d; asm("mov.b64 %0, {%1, %2};" : "=l"(d) : "f"(lo), "f"(hi)); return d;
}
__device__ __forceinline__ void unpack2_(u64t v, float& lo, float& hi) {
    asm("mov.b64 {%0, %1}, %2;" : "=f"(lo), "=f"(hi) : "l"(v));
}

// ---------------- LayerNorm ----------------
__global__ void __launch_bounds__(256) ln_kernel(
    const float* __restrict__ in, int istride, int width,
    float* __restrict__ out, int ostride,
    const float* __restrict__ w, const float* __restrict__ b)
{
    __shared__ float rowc[768];
    __shared__ float red[256];
    int r = blockIdx.x, tid = threadIdx.x;
    const float* ip = in + (size_t)r * istride;
    float s = 0.f;
    for (int i = tid; i < width; i += 256) { float v = ip[i]; rowc[i] = v; s += v; }
    red[tid] = s; __syncthreads();
    for (int st = 128; st > 0; st >>= 1) { if (tid < st) red[tid] += red[tid + st]; __syncthreads(); }
    float mean = red[0] / (float)width;
    __syncthreads();
    float s2 = 0.f;
    for (int i = tid; i < width; i += 256) { float d = rowc[i] - mean; s2 += d * d; }
    red[tid] = s2; __syncthreads();
    for (int st = 128; st > 0; st >>= 1) { if (tid < st) red[tid] += red[tid + st]; __syncthreads(); }
    float inv = rsqrtf(red[0] / (float)width + 1e-5f);
    float* op = out + (size_t)r * ostride;
    for (int i = tid; i < width; i += 256) {
        float v = (rowc[i] - mean) * inv * w[i];
        if (b) v += b[i];
        op[i] = v;
    }
}

// ---------------- TF32 tensor-core GEMM, 128x128x32, double-buffered ----------------
#define SK 36
#define STGW (128 * SK)   // words per stage per tensor

__device__ __forceinline__ unsigned f2tf32(float v) {
    unsigned u;
    asm("cvt.rna.tf32.f32 %0, %1;" : "=r"(u) : "f"(v));
    return u;
}

__device__ __forceinline__ void mma_tf32(float* c, const unsigned* a, const unsigned* b) {
    asm volatile("mma.sync.aligned.m16n8k8.row.col.f32.tf32.tf32.f32 "
                 "{%0,%1,%2,%3}, {%4,%5,%6,%7}, {%8,%9}, {%0,%1,%2,%3};"
                 : "+f"(c[0]), "+f"(c[1]), "+f"(c[2]), "+f"(c[3])
                 : "r"(a[0]), "r"(a[1]), "r"(a[2]), "r"(a[3]),
                   "r"(b[0]), "r"(b[1]));
}

template<int BT>
__global__ void __launch_bounds__(256) gemm_kernel(
    const float* __restrict__ A, int lda,
    const float* __restrict__ B, int ldb,
    float* __restrict__ C, int ldc,
    int M, int N, int K,
    int doGelu,
    const float* __restrict__ addC,
    const int* __restrict__ tokList, const float* __restrict__ gateList,
    const int* __restrict__ slotList, int listBase,
    const int* __restrict__ offArr, const int* __restrict__ cntArr, int eIdx,
    int amode, int cmode)
{
    int Mreal = cntArr ? cntArr[eIdx] : M;
    int mt = blockIdx.y * 128, nt = blockIdx.x * 128;
    if (mt >= Mreal) return;
    int offv = offArr ? offArr[eIdx] : 0;

    extern __shared__ unsigned smemu[];
    unsigned* Asb = smemu;              // 2 stages of 128 x SK
    unsigned* Bsb = smemu + 2 * STGW;   // 2 stages of 128 x SK

    int tid = threadIdx.x;
    int wid = tid >> 5, lane = tid & 31;
    int wm = wid & 3, wn = wid >> 2;    // warp tile rows wm*32, cols wn*64
    int lrow = lane >> 2;
    int lcol = lane & 3;

    float acc[2][8][4];
#pragma unroll
    for (int i = 0; i < 2; i++)
#pragma unroll
        for (int j = 0; j < 8; j++)
#pragma unroll
            for (int r = 0; r < 4; r++) acc[i][j][r] = 0.f;

    // fill-thread mapping
    int fr = tid >> 3, ff = tid & 7;     // fr: 0..31 (row group), ff: float4 col within 32-k
    // gather rows for A (constant across k)
    int arowv[4]; bool aval[4];
#pragma unroll
    for (int i = 0; i < 4; i++) {
        int gm = mt + fr + i * 32;
        aval[i] = gm < Mreal;
        int arow = 0;
        if (aval[i]) {
            if (amode == 0) arow = gm;
            else if (amode == 1) arow = tokList[listBase + gm];
            else arow = offv + gm;
        }
        arowv[i] = arow;
    }
    // B row info
    bool bval[4];
    int kr_ = tid >> 5, n4 = tid & 31;   // for BT==0 path
    if (BT == 1) {
#pragma unroll
        for (int i = 0; i < 4; i++) bval[i] = (nt + fr + i * 32) < N;
    } else {
#pragma unroll
        for (int i = 0; i < 4; i++) bval[i] = (nt + n4 * 4) < N;
    }

    float4 pa[4], pb[4];
    const float4 z4 = make_float4(0.f, 0.f, 0.f, 0.f);

    auto ldgA = [&](int k0) {
#pragma unroll
        for (int i = 0; i < 4; i++)
            pa[i] = aval[i] ? *reinterpret_cast<const float4*>(A + (size_t)arowv[i] * lda + k0 + ff * 4) : z4;
    };
    auto ldgB = [&](int k0) {
        if (BT == 1) {
#pragma unroll
            for (int i = 0; i < 4; i++)
                pb[i] = bval[i] ? *reinterpret_cast<const float4*>(B + (size_t)(nt + fr + i * 32) * ldb + k0 + ff * 4) : z4;
        } else {
#pragma unroll
            for (int i = 0; i < 4; i++)
                pb[i] = bval[i] ? *reinterpret_cast<const float4*>(B + (size_t)(k0 + kr_ + i * 8) * ldb + nt + n4 * 4) : z4;
        }
    };
    auto stsA = [&](int s) {
#pragma unroll
        for (int i = 0; i < 4; i++) {
            uint4 u = make_uint4(f2tf32(pa[i].x), f2tf32(pa[i].y), f2tf32(pa[i].z), f2tf32(pa[i].w));
            *reinterpret_cast<uint4*>(&Asb[s * STGW + (fr + i * 32) * SK + ff * 4]) = u;
        }
    };
    auto stsB = [&](int s) {
        if (BT == 1) {
#pragma unroll
            for (int i = 0; i < 4; i++) {
                uint4 u = make_uint4(f2tf32(pb[i].x), f2tf32(pb[i].y), f2tf32(pb[i].z), f2tf32(pb[i].w));
                *reinterpret_cast<uint4*>(&Bsb[s * STGW + (fr + i * 32) * SK + ff * 4]) = u;
            }
        } else {
#pragma unroll
            for (int i = 0; i < 4; i++) {
                int kk = kr_ + i * 8;
                Bsb[s * STGW + (n4 * 4 + 0) * SK + kk] = f2tf32(pb[i].x);
                Bsb[s * STGW + (n4 * 4 + 1) * SK + kk] = f2tf32(pb[i].y);
                Bsb[s * STGW + (n4 * 4 + 2) * SK + kk] = f2tf32(pb[i].z);
                Bsb[s * STGW + (n4 * 4 + 3) * SK + kk] = f2tf32(pb[i].w);
            }
        }
    };
    auto compute = [&](int s) {
        const unsigned* As = Asb + s * STGW;
        const unsigned* Bs = Bsb + s * STGW;
#pragma unroll
        for (int ks = 0; ks < 4; ks++) {
            int kb = ks * 8;
            unsigned a[2][4];
#pragma unroll
            for (int m2 = 0; m2 < 2; m2++) {
                int r0 = wm * 32 + m2 * 16 + lrow;
                a[m2][0] = As[r0 * SK + kb + lcol];
                a[m2][1] = As[(r0 + 8) * SK + kb + lcol];
                a[m2][2] = As[r0 * SK + kb + 4 + lcol];
                a[m2][3] = As[(r0 + 8) * SK + kb + 4 + lcol];
            }
            unsigned b[8][2];
#pragma unroll
            for (int n2 = 0; n2 < 8; n2++) {
                int nn = wn * 64 + n2 * 8 + lrow;
                b[n2][0] = Bs[nn * SK + kb + lcol];
                b[n2][1] = Bs[nn * SK + kb + 4 + lcol];
            }
#pragma unroll
            for (int m2 = 0; m2 < 2; m2++)
#pragma unroll
                for (int n2 = 0; n2 < 8; n2++)
                    mma_tf32(acc[m2][n2], a[m2], b[n2]);
        }
    };

    int nk = K / 32;
    ldgA(0); ldgB(0);
    stsA(0); stsB(0);
    __syncthreads();
    for (int kt = 0; kt < nk; kt++) {
        int s = kt & 1;
        bool more = (kt + 1) < nk;
        if (more) { ldgA((kt + 1) * 32); ldgB((kt + 1) * 32); }
        compute(s);
        if (more) { stsA(s ^ 1); stsB(s ^ 1); }
        __syncthreads();
    }

    // epilogue
#pragma unroll
    for (int m2 = 0; m2 < 2; m2++) {
#pragma unroll
        for (int ri = 0; ri < 2; ri++) {
            int gm = mt + wm * 32 + m2 * 16 + lrow + ri * 8;
            if (gm >= Mreal) continue;
            int crow; float scale = 1.f;
            if (cmode == 0) crow = gm;
            else if (cmode == 1) crow = offv + gm;
            else {
                crow = slotList[listBase + gm] * TT + tokList[listBase + gm];
                scale = gateList[listBase + gm];
            }
#pragma unroll
            for (int n2 = 0; n2 < 8; n2++) {
#pragma unroll
                for (int cj = 0; cj < 2; cj++) {
                    int gn = nt + wn * 64 + n2 * 8 + lcol * 2 + cj;
                    if (gn >= N) continue;
                    float v = acc[m2][n2][ri * 2 + cj];
                    if (doGelu) v = 0.5f * v * (1.f + erff(v * 0.70710678118654752f));
                    v *= scale;
                    if (addC) v += addC[(size_t)crow * ldc + gn];
                    C[(size_t)crow * ldc + gn] = v;
                }
            }
        }
    }
}

// ---------------- RoPE ----------------
__global__ void rope_q_kernel(float* __restrict__ q)
{
    int idx = blockIdx.x * blockDim.x + threadIdx.x;
    if (idx >= TT * HH * 16) return;
    int j = idx & 15;
    int h = (idx >> 4) % HH;
    int t = idx / (HH * 16);
    int s = t & (SS - 1);
    float f = powf(10000.f, -(float)j / 32.f);
    float a = (float)s * f;
    float c = cosf(a), sn = sinf(a);
    size_t base = (size_t)t * DD + h * DHH + NOPE_;
    float x1 = q[base + j];
    float x2 = q[base + 16 + j];
    q[base + j]      = x1 * c - x2 * sn;
    q[base + 16 + j] = x2 * c + x1 * sn;
}

__global__ void rope_k_kernel(const float* __restrict__ ckv, float* __restrict__ kr)
{
    int idx = blockIdx.x * blockDim.x + threadIdx.x;
    if (idx >= TT * 16) return;
    int j = idx & 15;
    int t = idx >> 4;
    int s = t & (SS - 1);
    float f = powf(10000.f, -(float)j / 32.f);
    float a = (float)s * f;
    float c = cosf(a), sn = sinf(a);
    size_t base = (size_t)t * KVW_ + KVP_;
    float x1 = ckv[base + j];
    float x2 = ckv[base + 16 + j];
    kr[(size_t)t * ROPE_ + j]      = x1 * c - x2 * sn;
    kr[(size_t)t * ROPE_ + 16 + j] = x2 * c + x1 * sn;
}

// ---------------- causal flash attention v2 (f32x2 packed) ----------------
// block 256 = 64 queries x 4 key-subsets; Q in registers; per-thread online softmax
// over its key subset; final 4-lane shfl merge.
__global__ void __launch_bounds__(256) attn_kernel(
    const float* __restrict__ Q, const float* __restrict__ kvu,
    const float* __restrict__ kr, float* __restrict__ O)
{
    int qt = blockIdx.x, h = blockIdx.y, b = blockIdx.z;
    int tid = threadIdx.x;
    int q = tid >> 2, kq = tid & 3;
    int qi = qt * 64 + q;
    int t0 = b * SS;

    __shared__ __align__(16) float ks[32][68];
    __shared__ __align__(16) float vs[32][68];

    // Q into registers, packed pairs (64 dims = 32 u64)
    u64t qreg[32];
    {
        const float* qp = Q + (size_t)(t0 + qi) * DD + h * DHH;
#pragma unroll
        for (int i = 0; i < 16; i++) {
            ulonglong2 v = *reinterpret_cast<const ulonglong2*>(qp + i * 4);
            qreg[2 * i] = v.x; qreg[2 * i + 1] = v.y;
        }
    }

    u64t acc2[32];
#pragma unroll
    for (int i = 0; i < 32; i++) acc2[i] = 0ull;
    float mcur = -3.0e38f, l = 0.f;

    int ntiles = 2 * qt + 2;
    for (int kt = 0; kt < ntiles; kt++) {
        int kb = kt * 32;
        // fill 32x64 K and V tiles
#pragma unroll
        for (int i = 0; i < 8; i++) {
            int idx = tid + i * 256;
            int z = idx >> 6, d = idx & 63;
            int kg = t0 + kb + z;
            ks[z][d] = (d < 32) ? kvu[(size_t)kg * UKV_ + h * 96 + d]
                                : kr[(size_t)kg * ROPE_ + (d - 32)];
            vs[z][d] = kvu[(size_t)kg * UKV_ + h * 96 + 32 + d];
        }
        __syncthreads();

#pragma unroll 2
        for (int jj = 0; jj < 8; jj++) {
            int j = jj * 4 + kq;
            if (kb + j <= qi) {
                // score = qreg . ks[j]
                const ulonglong2* kp = reinterpret_cast<const ulonglong2*>(&ks[j][0]);
                u64t sa = 0ull, sb = 0ull;
#pragma unroll
                for (int i = 0; i < 16; i++) {
                    ulonglong2 kv = kp[i];
                    sa = fma2_(qreg[2 * i], kv.x, sa);
                    sb = fma2_(qreg[2 * i + 1], kv.y, sb);
                }
                float f0, f1, f2, f3;
                unpack2_(sa, f0, f1); unpack2_(sb, f2, f3);
                float s = ((f0 + f1) + (f2 + f3)) * 0.125f;
                if (s > mcur) {
                    float corr = __expf(mcur - s);
                    l *= corr;
                    u64t c2 = pack2_(corr, corr);
#pragma unroll
                    for (int i = 0; i < 32; i++) acc2[i] = mul2_(acc2[i], c2);
                    mcur = s;
                }
                float p = __expf(s - mcur);
                l += p;
                u64t p2 = pack2_(p, p);
                const ulonglong2* vp = reinterpret_cast<const ulonglong2*>(&vs[j][0]);
#pragma unroll
                for (int i = 0; i < 16; i++) {
                    ulonglong2 vv = vp[i];
                    acc2[2 * i]     = fma2_(p2, vv.x, acc2[2 * i]);
                    acc2[2 * i + 1] = fma2_(p2, vv.y, acc2[2 * i + 1]);
                }
            }
        }
        __syncthreads();
    }

    // merge across the 4 kq lanes
    float mmax = mcur;
    mmax = fmaxf(mmax, __shfl_xor_sync(0xffffffffu, mmax, 1));
    mmax = fmaxf(mmax, __shfl_xor_sync(0xffffffffu, mmax, 2));
    float c = __expf(mcur - mmax);
    l *= c;
    l += __shfl_xor_sync(0xffffffffu, l, 1);
    l += __shfl_xor_sync(0xffffffffu, l, 2);
    u64t c2 = pack2_(c, c);
#pragma unroll
    for (int i = 0; i < 32; i++) {
        acc2[i] = mul2_(acc2[i], c2);
        acc2[i] = add2_(acc2[i], __shfl_xor_sync(0xffffffffu, acc2[i], 1));
        acc2[i] = add2_(acc2[i], __shfl_xor_sync(0xffffffffu, acc2[i], 2));
    }
    float invl = 1.f / l;
    float* op = O + (size_t)(t0 + qi) * DD + h * DHH + kq * 16;
#pragma unroll
    for (int i = 0; i < 8; i++) {
        float lo, hi;
        unpack2_(acc2[kq * 8 + i], lo, hi);
        op[2 * i] = lo * invl;
        op[2 * i + 1] = hi * invl;
    }
}

// ---------------- routing ----------------
__global__ void route_kernel(const float* __restrict__ h2,
                             const float* __restrict__ cent,
                             const float* __restrict__ bias,
                             int* __restrict__ tope, float* __restrict__ topg)
{
    int warp = (blockIdx.x * blockDim.x + threadIdx.x) >> 5;
    int lane = threadIdx.x & 31;
    if (warp >= TT) return;
    const float* hp = h2 + (size_t)warp * DD;
    float raw[EE];
    for (int e = 0; e < EE; e++) {
        const float* cp = cent + (size_t)e * DD;
        float p = 0.f;
        for (int d = lane; d < DD; d += 32) p += hp[d] * cp[d];
#pragma unroll
        for (int o = 16; o > 0; o >>= 1) p += __shfl_xor_sync(0xffffffff, p, o);
        raw[e] = p;
    }
    if (lane == 0) {
        int i0 = 0, i1 = -1;
        float b0 = -3.4e38f, b1 = -3.4e38f;
        for (int e = 0; e < EE; e++) { float v = raw[e] + bias[e]; if (v > b0) { b0 = v; i0 = e; } }
        for (int e = 0; e < EE; e++) { if (e == i0) continue; float v = raw[e] + bias[e]; if (v > b1) { b1 = v; i1 = e; } }
        float g0 = 1.f / (1.f + expf(-raw[i0]));
        float g1 = 1.f / (1.f + expf(-raw[i1]));
        float sg = g0 + g1 + 1e-9f;
        tope[warp * 2] = i0; tope[warp * 2 + 1] = i1;
        topg[warp * 2] = g0 / sg; topg[warp * 2 + 1] = g1 / sg;
    }
}

// ---------------- per-expert list build ----------------
__global__ void build_lists_kernel(const int* __restrict__ tope, const float* __restrict__ topg,
                                   int* __restrict__ eidx, float* __restrict__ egate,
                                   int* __restrict__ eslot, int* __restrict__ cnt)
{
    int e = blockIdx.x;
    int tid = threadIdx.x;
    __shared__ int c[256];
    int t0 = tid * 16;
    int lc = 0;
    for (int i = 0; i < 16; i++) {
        int t = t0 + i;
        lc += (tope[t * 2] == e) || (tope[t * 2 + 1] == e);
    }
    c[tid] = lc; __syncthreads();
    if (tid == 0) {
        int tot = 0;
        for (int i = 0; i < 256; i++) { int v = c[i]; c[i] = tot; tot += v; }
        cnt[e] = tot;
    }
    __syncthreads();
    int pos = c[tid];
    for (int i = 0; i < 16; i++) {
        int t = t0 + i;
        int slot = -1;
        if (tope[t * 2] == e) slot = 0;
        else if (tope[t * 2 + 1] == e) slot = 1;
        if (slot >= 0) {
            int p = e * TT + pos;
            eidx[p] = t;
            egate[p] = topg[t * 2 + slot];
            eslot[p] = slot;
            pos++;
        }
    }
}

__global__ void offsets_kernel(const int* __restrict__ cnt, int* __restrict__ off)
{
    if (threadIdx.x == 0) {
        int a = 0;
        for (int e = 0; e < EE; e++) { off[e] = a; a += cnt[e]; }
    }
}

// ---------------- final combine ----------------
__global__ void combine_kernel(const float* __restrict__ x2, const float* __restrict__ sh,
                               const float* __restrict__ slots, float* __restrict__ out)
{
    int i = blockIdx.x * 256 + threadIdx.x;
    if (i < TT * DD)
        out[i] = x2[i] + sh[i] + slots[i] + slots[TT * DD + i];
}

// ---------------- host launcher ----------------
#define GSMEM (4 * STGW * 4)   // 73728 bytes

static void launch_gemm(bool bt,
                        const float* A, int lda, const float* B, int ldb,
                        float* C, int ldc, int M, int N, int K,
                        bool gelu, const float* addC,
                        const int* tok, const float* gate, const int* slot, int listBase,
                        const int* offA, const int* cntA, int e,
                        int amode, int cmode)
{
    dim3 grid((N + 127) / 128, (M + 127) / 128);
    if (bt)
        gemm_kernel<1><<<grid, 256, GSMEM>>>(A, lda, B, ldb, C, ldc, M, N, K,
                                             gelu ? 1 : 0, addC, tok, gate, slot, listBase,
                                             offA, cntA, e, amode, cmode);
    else
        gemm_kernel<0><<<grid, 256, GSMEM>>>(A, lda, B, ldb, C, ldc, M, N, K,
                                             gelu ? 1 : 0, addC, tok, gate, slot, listBase,
                                             offA, cntA, e, amode, cmode);
}

extern "C" void kernel_launch(void* const* d_in, const int* in_sizes, int n_in,
                              void* d_out, int out_size)
{
    const float* x       = (const float*)d_in[0];
    const float* ln1_w   = (const float*)d_in[1];
    const float* ln2_w   = (const float*)d_in[2];
    const float* W_dq    = (const float*)d_in[3];
    const float* W_uq    = (const float*)d_in[4];
    const float* q_ln_w  = (const float*)d_in[5];
    const float* q_ln_b  = (const float*)d_in[6];
    const float* W_dkv   = (const float*)d_in[7];
    const float* W_ukv   = (const float*)d_in[8];
    const float* kv_ln_w = (const float*)d_in[9];
    const float* kv_ln_b = (const float*)d_in[10];
    const float* W_o     = (const float*)d_in[11];
    const float* s_fc    = (const float*)d_in[12];
    const float* s_proj  = (const float*)d_in[13];
    const float* e_fc    = (const float*)d_in[14];
    const float* e_proj  = (const float*)d_in[15];
    const float* cent    = (const float*)d_in[16];
    const float* rbias   = (const float*)d_in[17];
    float* out = (float*)d_out;

    cudaFuncSetAttribute(gemm_kernel<0>, cudaFuncAttributeMaxDynamicSharedMemorySize, GSMEM);
    cudaFuncSetAttribute(gemm_kernel<1>, cudaFuncAttributeMaxDynamicSharedMemorySize, GSMEM);

    float *h1, *cq, *q, *ckv, *kvl, *kvu, *kr, *ao, *x2, *h2, *sh, *hid, *ehid, *slots, *egate, *topg;
    int *eidx, *eslot, *cnt, *off, *tope;
    cudaGetSymbolAddress((void**)&h1, g_h1);
    cudaGetSymbolAddress((void**)&cq, g_cq);
    cudaGetSymbolAddress((void**)&q, g_q);
    cudaGetSymbolAddress((void**)&ckv, g_ckv);
    cudaGetSymbolAddress((void**)&kvl, g_kvl);
    cudaGetSymbolAddress((void**)&kvu, g_kvu);
    cudaGetSymbolAddress((void**)&kr, g_kr);
    cudaGetSymbolAddress((void**)&ao, g_ao);
    cudaGetSymbolAddress((void**)&x2, g_x2);
    cudaGetSymbolAddress((void**)&h2, g_h2);
    cudaGetSymbolAddress((void**)&sh, g_sh);
    cudaGetSymbolAddress((void**)&hid, g_hid);
    cudaGetSymbolAddress((void**)&ehid, g_ehid);
    cudaGetSymbolAddress((void**)&slots, g_slots);
    cudaGetSymbolAddress((void**)&egate, g_egate);
    cudaGetSymbolAddress((void**)&topg, g_topg);
    cudaGetSymbolAddress((void**)&eidx, g_eidx);
    cudaGetSymbolAddress((void**)&eslot, g_eslot);
    cudaGetSymbolAddress((void**)&cnt, g_cnt);
    cudaGetSymbolAddress((void**)&off, g_off);
    cudaGetSymbolAddress((void**)&tope, g_tope);

    ln_kernel<<<TT, 256>>>(x, DD, DD, h1, DD, ln1_w, nullptr);
    launch_gemm(false, h1, DD, W_dq, QP_, cq, QP_, TT, QP_, DD,
                false, nullptr, nullptr, nullptr, nullptr, 0, nullptr, nullptr, 0, 0, 0);
    ln_kernel<<<TT, 256>>>(cq, QP_, QP_, cq, QP_, q_ln_w, q_ln_b);
    launch_gemm(false, cq, QP_, W_uq, DD, q, DD, TT, DD, QP_,
                false, nullptr, nullptr, nullptr, nullptr, 0, nullptr, nullptr, 0, 0, 0);
    launch_gemm(false, h1, DD, W_dkv, KVW_, ckv, KVW_, TT, KVW_, DD,
                false, nullptr, nullptr, nullptr, nullptr, 0, nullptr, nullptr, 0, 0, 0);
    ln_kernel<<<TT, 256>>>(ckv, KVW_, KVP_, kvl, KVP_, kv_ln_w, kv_ln_b);
    launch_gemm(false, kvl, KVP_, W_ukv, UKV_, kvu, UKV_, TT, UKV_, KVP_,
                false, nullptr, nullptr, nullptr, nullptr, 0, nullptr, nullptr, 0, 0, 0);
    rope_q_kernel<<<(TT * HH * 16 + 255) / 256, 256>>>(q);
    rope_k_kernel<<<(TT * 16 + 255) / 256, 256>>>(ckv, kr);
    {
        dim3 agrid(SS / 64, HH, BB);
        attn_kernel<<<agrid, 256>>>(q, kvu, kr, ao);
    }
    launch_gemm(true, ao, DD, W_o, DD, x2, DD, TT, DD, DD,
                false, x, nullptr, nullptr, nullptr, 0, nullptr, nullptr, 0, 0, 0);
    ln_kernel<<<TT, 256>>>(x2, DD, DD, h2, DD, ln2_w, nullptr);
    for (int n = 0; n < 2; n++) {
        launch_gemm(true, h2, DD, s_fc + (size_t)n * FF_ * DD, DD, hid, FF_, TT, FF_, DD,
                    true, nullptr, nullptr, nullptr, nullptr, 0, nullptr, nullptr, 0, 0, 0);
        launch_gemm(true, hid, FF_, s_proj + (size_t)n * DD * FF_, FF_, sh, DD, TT, DD, FF_,
                    false, n == 0 ? nullptr : sh,
                    nullptr, nullptr, nullptr, 0, nullptr, nullptr, 0, 0, 0);
    }
    route_kernel<<<TT / 4, 128>>>(h2, cent, rbias, tope, topg);
    build_lists_kernel<<<EE, 256>>>(tope, topg, eidx, egate, eslot, cnt);
    offsets_kernel<<<1, 32>>>(cnt, off);
    for (int e = 0; e < EE; e++) {
        launch_gemm(true, h2, DD, e_fc + (size_t)e * FF_ * DD, DD, ehid, FF_, TT, FF_, DD,
                    true, nullptr, eidx, egate, eslot, e * TT, off, cnt, e, 1, 1);
    }
    for (int e = 0; e < EE; e++) {
        launch_gemm(true, ehid, FF_, e_proj + (size_t)e * DD * FF_, FF_, slots, DD, TT, DD, FF_,
                    false, nullptr, eidx, egate, eslot, e * TT, off, cnt, e, 2, 2);
    }
    combine_kernel<<<(TT * DD + 255) / 256, 256>>>(x2, sh, slots, out);
}

// round 4
// speedup vs baseline: 4.9374x; 1.3613x over previous
#include <cuda_runtime.h>
#include <math.h>

// ---------------- problem constants ----------------
#define BB    4
#define SS    1024
#define TT    4096
#define DD    768
#define HH    12
#define DHH   64
#define NOPE_ 32
#define ROPE_ 32
#define QP_   384
#define KVP_  512
#define KVW_  544
#define UKV_  1152
#define EE    8
#define FF_   3072

// ---------------- scratch ----------------
__device__ __align__(256) float g_h1[TT * DD];
__device__ __align__(256) float g_cq[TT * QP_];
__device__ __align__(256) float g_q[TT * DD];
__device__ __align__(256) float g_ckv[TT * KVW_];
__device__ __align__(256) float g_kvl[TT * KVP_];
__device__ __align__(256) float g_kvu[TT * UKV_];
__device__ __align__(256) float g_kr[TT * ROPE_];
__device__ __align__(256) float g_ao[TT * DD];
__device__ __align__(256) float g_x2[TT * DD];
__device__ __align__(256) float g_h2[TT * DD];
__device__ __align__(256) float g_sh[2 * TT * DD];     // per shared-expert outputs
__device__ __align__(256) float g_hid[2 * TT * FF_];   // per shared-expert hidden
__device__ __align__(256) float g_ehid[2 * TT * FF_];  // routed hidden, compact
__device__ __align__(256) float g_slots[2 * TT * DD];  // routed output per top-k slot
__device__ int   g_tope[TT * 2];
__device__ float g_topg[TT * 2];
__device__ int   g_eidx[EE * TT];
__device__ float g_egate[EE * TT];
__device__ int   g_eslot[EE * TT];
__device__ int   g_cnt[EE];
__device__ int   g_off[EE];

// ---------------- f32x2 packed helpers ----------------
typedef unsigned long long u64t;
__device__ __forceinline__ u64t fma2_(u64t a, u64t b, u64t c) {
    u64t d; asm("fma.rn.f32x2 %0, %1, %2, %3;" : "=l"(d) : "l"(a), "l"(b), "l"(c)); return d;
}
__device__ __forceinline__ u64t mul2_(u64t a, u64t b) {
    u64t d; asm("mul.rn.f32x2 %0, %1, %2;" : "=l"(d) : "l"(a), "l"(b)); return d;
}
__device__ __forceinline__ u64t add2_(u64t a, u64t b) {
    u64t d; asm("add.rn.f32x2 %0, %1, %2;" : "=l"(d) : "l"(a), "l"(b)); return d;
}
__device__ __forceinline__ u64t pack2_(float lo, float hi) {
    u64t d; asm("mov.b64 %0, {%1, %2};" : "=l"(d) : "f"(lo), "f"(hi)); return d;
}
__device__ __forceinline__ void unpack2_(u64t v, float& lo, float& hi) {
    asm("mov.b64 {%0, %1}, %2;" : "=f"(lo), "=f"(hi) : "l"(v));
}

// ---------------- LayerNorm ----------------
__global__ void __launch_bounds__(256) ln_kernel(
    const float* __restrict__ in, int istride, int width,
    float* __restrict__ out, int ostride,
    const float* __restrict__ w, const float* __restrict__ b)
{
    __shared__ float rowc[768];
    __shared__ float red[256];
    int r = blockIdx.x, tid = threadIdx.x;
    const float* ip = in + (size_t)r * istride;
    float s = 0.f;
    for (int i = tid; i < width; i += 256) { float v = ip[i]; rowc[i] = v; s += v; }
    red[tid] = s; __syncthreads();
    for (int st = 128; st > 0; st >>= 1) { if (tid < st) red[tid] += red[tid + st]; __syncthreads(); }
    float mean = red[0] / (float)width;
    __syncthreads();
    float s2 = 0.f;
    for (int i = tid; i < width; i += 256) { float d = rowc[i] - mean; s2 += d * d; }
    red[tid] = s2; __syncthreads();
    for (int st = 128; st > 0; st >>= 1) { if (tid < st) red[tid] += red[tid + st]; __syncthreads(); }
    float inv = rsqrtf(red[0] / (float)width + 1e-5f);
    float* op = out + (size_t)r * ostride;
    for (int i = tid; i < width; i += 256) {
        float v = (rowc[i] - mean) * inv * w[i];
        if (b) v += b[i];
        op[i] = v;
    }
}

// ---------------- TF32 tensor-core GEMM, 128x128x32, double-buffered, z-batched ----------------
#define SK 36
#define STGW (128 * SK)

__device__ __forceinline__ unsigned f2tf32(float v) {
    unsigned u;
    asm("cvt.rna.tf32.f32 %0, %1;" : "=r"(u) : "f"(v));
    return u;
}

__device__ __forceinline__ void mma_tf32(float* c, const unsigned* a, const unsigned* b) {
    asm volatile("mma.sync.aligned.m16n8k8.row.col.f32.tf32.tf32.f32 "
                 "{%0,%1,%2,%3}, {%4,%5,%6,%7}, {%8,%9}, {%0,%1,%2,%3};"
                 : "+f"(c[0]), "+f"(c[1]), "+f"(c[2]), "+f"(c[3])
                 : "r"(a[0]), "r"(a[1]), "r"(a[2]), "r"(a[3]),
                   "r"(b[0]), "r"(b[1]));
}

// amode: 0 arow=m; 1 arow=tokList[z*TT+m]; 2 arow=off[z]+m
// cmode: 0 crow=m; 1 crow=off[z]+m; 2 crow=slot*TT+tok (scaled by gate)
template<int BT>
__global__ void __launch_bounds__(256) gemm_kernel(
    const float* __restrict__ A, int lda, long azs,
    const float* __restrict__ B, int ldb, long bzs,
    float* __restrict__ C, int ldc, long czs,
    int M, int N, int K,
    int doGelu,
    const float* __restrict__ addC,
    const int* __restrict__ tokList, const float* __restrict__ gateList,
    const int* __restrict__ slotList,
    const int* __restrict__ offArr, const int* __restrict__ cntArr,
    int amode, int cmode)
{
    int z = blockIdx.z;
    int Mreal = cntArr ? cntArr[z] : M;
    int mt = blockIdx.y * 128, nt = blockIdx.x * 128;
    if (mt >= Mreal) return;
    int offv = offArr ? offArr[z] : 0;
    int listBase = z * TT;
    A += (size_t)z * azs;
    B += (size_t)z * bzs;
    C += (size_t)z * czs;

    extern __shared__ unsigned smemu[];
    unsigned* Asb = smemu;
    unsigned* Bsb = smemu + 2 * STGW;

    int tid = threadIdx.x;
    int wid = tid >> 5, lane = tid & 31;
    int wm = wid & 3, wn = wid >> 2;
    int lrow = lane >> 2;
    int lcol = lane & 3;

    float acc[2][8][4];
#pragma unroll
    for (int i = 0; i < 2; i++)
#pragma unroll
        for (int j = 0; j < 8; j++)
#pragma unroll
            for (int r = 0; r < 4; r++) acc[i][j][r] = 0.f;

    int fr = tid >> 3, ff = tid & 7;
    int arowv[4]; bool aval[4];
#pragma unroll
    for (int i = 0; i < 4; i++) {
        int gm = mt + fr + i * 32;
        aval[i] = gm < Mreal;
        int arow = 0;
        if (aval[i]) {
            if (amode == 0) arow = gm;
            else if (amode == 1) arow = tokList[listBase + gm];
            else arow = offv + gm;
        }
        arowv[i] = arow;
    }
    bool bval[4];
    int kr_ = tid >> 5, n4 = tid & 31;
    if (BT == 1) {
#pragma unroll
        for (int i = 0; i < 4; i++) bval[i] = (nt + fr + i * 32) < N;
    } else {
#pragma unroll
        for (int i = 0; i < 4; i++) bval[i] = (nt + n4 * 4) < N;
    }

    float4 pa[4], pb[4];
    const float4 z4 = make_float4(0.f, 0.f, 0.f, 0.f);

    auto ldgA = [&](int k0) {
#pragma unroll
        for (int i = 0; i < 4; i++)
            pa[i] = aval[i] ? *reinterpret_cast<const float4*>(A + (size_t)arowv[i] * lda + k0 + ff * 4) : z4;
    };
    auto ldgB = [&](int k0) {
        if (BT == 1) {
#pragma unroll
            for (int i = 0; i < 4; i++)
                pb[i] = bval[i] ? *reinterpret_cast<const float4*>(B + (size_t)(nt + fr + i * 32) * ldb + k0 + ff * 4) : z4;
        } else {
#pragma unroll
            for (int i = 0; i < 4; i++)
                pb[i] = bval[i] ? *reinterpret_cast<const float4*>(B + (size_t)(k0 + kr_ + i * 8) * ldb + nt + n4 * 4) : z4;
        }
    };
    auto stsA = [&](int s) {
#pragma unroll
        for (int i = 0; i < 4; i++) {
            uint4 u = make_uint4(f2tf32(pa[i].x), f2tf32(pa[i].y), f2tf32(pa[i].z), f2tf32(pa[i].w));
            *reinterpret_cast<uint4*>(&Asb[s * STGW + (fr + i * 32) * SK + ff * 4]) = u;
        }
    };
    auto stsB = [&](int s) {
        if (BT == 1) {
#pragma unroll
            for (int i = 0; i < 4; i++) {
                uint4 u = make_uint4(f2tf32(pb[i].x), f2tf32(pb[i].y), f2tf32(pb[i].z), f2tf32(pb[i].w));
                *reinterpret_cast<uint4*>(&Bsb[s * STGW + (fr + i * 32) * SK + ff * 4]) = u;
            }
        } else {
#pragma unroll
            for (int i = 0; i < 4; i++) {
                int kk = kr_ + i * 8;
                Bsb[s * STGW + (n4 * 4 + 0) * SK + kk] = f2tf32(pb[i].x);
                Bsb[s * STGW + (n4 * 4 + 1) * SK + kk] = f2tf32(pb[i].y);
                Bsb[s * STGW + (n4 * 4 + 2) * SK + kk] = f2tf32(pb[i].z);
                Bsb[s * STGW + (n4 * 4 + 3) * SK + kk] = f2tf32(pb[i].w);
            }
        }
    };
    auto compute = [&](int s) {
        const unsigned* As = Asb + s * STGW;
        const unsigned* Bs = Bsb + s * STGW;
#pragma unroll
        for (int ks = 0; ks < 4; ks++) {
            int kb = ks * 8;
            unsigned a[2][4];
#pragma unroll
            for (int m2 = 0; m2 < 2; m2++) {
                int r0 = wm * 32 + m2 * 16 + lrow;
                a[m2][0] = As[r0 * SK + kb + lcol];
                a[m2][1] = As[(r0 + 8) * SK + kb + lcol];
                a[m2][2] = As[r0 * SK + kb + 4 + lcol];
                a[m2][3] = As[(r0 + 8) * SK + kb + 4 + lcol];
            }
            unsigned b[8][2];
#pragma unroll
            for (int n2 = 0; n2 < 8; n2++) {
                int nn = wn * 64 + n2 * 8 + lrow;
                b[n2][0] = Bs[nn * SK + kb + lcol];
                b[n2][1] = Bs[nn * SK + kb + 4 + lcol];
            }
#pragma unroll
            for (int m2 = 0; m2 < 2; m2++)
#pragma unroll
                for (int n2 = 0; n2 < 8; n2++)
                    mma_tf32(acc[m2][n2], a[m2], b[n2]);
        }
    };

    int nk = K / 32;
    ldgA(0); ldgB(0);
    stsA(0); stsB(0);
    __syncthreads();
    for (int kt = 0; kt < nk; kt++) {
        int s = kt & 1;
        bool more = (kt + 1) < nk;
        if (more) { ldgA((kt + 1) * 32); ldgB((kt + 1) * 32); }
        compute(s);
        if (more) { stsA(s ^ 1); stsB(s ^ 1); }
        __syncthreads();
    }

#pragma unroll
    for (int m2 = 0; m2 < 2; m2++) {
#pragma unroll
        for (int ri = 0; ri < 2; ri++) {
            int gm = mt + wm * 32 + m2 * 16 + lrow + ri * 8;
            if (gm >= Mreal) continue;
            int crow; float scale = 1.f;
            if (cmode == 0) crow = gm;
            else if (cmode == 1) crow = offv + gm;
            else {
                crow = slotList[listBase + gm] * TT + tokList[listBase + gm];
                scale = gateList[listBase + gm];
            }
#pragma unroll
            for (int n2 = 0; n2 < 8; n2++) {
#pragma unroll
                for (int cj = 0; cj < 2; cj++) {
                    int gn = nt + wn * 64 + n2 * 8 + lcol * 2 + cj;
                    if (gn >= N) continue;
                    float v = acc[m2][n2][ri * 2 + cj];
                    if (doGelu) v = 0.5f * v * (1.f + erff(v * 0.70710678118654752f));
                    v *= scale;
                    if (addC) v += addC[(size_t)crow * ldc + gn];
                    C[(size_t)crow * ldc + gn] = v;
                }
            }
        }
    }
}

// ---------------- RoPE ----------------
__global__ void rope_q_kernel(float* __restrict__ q)
{
    int idx = blockIdx.x * blockDim.x + threadIdx.x;
    if (idx >= TT * HH * 16) return;
    int j = idx & 15;
    int h = (idx >> 4) % HH;
    int t = idx / (HH * 16);
    int s = t & (SS - 1);
    float f = powf(10000.f, -(float)j / 32.f);
    float a = (float)s * f;
    float c = cosf(a), sn = sinf(a);
    size_t base = (size_t)t * DD + h * DHH + NOPE_;
    float x1 = q[base + j];
    float x2 = q[base + 16 + j];
    q[base + j]      = x1 * c - x2 * sn;
    q[base + 16 + j] = x2 * c + x1 * sn;
}

__global__ void rope_k_kernel(const float* __restrict__ ckv, float* __restrict__ kr)
{
    int idx = blockIdx.x * blockDim.x + threadIdx.x;
    if (idx >= TT * 16) return;
    int j = idx & 15;
    int t = idx >> 4;
    int s = t & (SS - 1);
    float f = powf(10000.f, -(float)j / 32.f);
    float a = (float)s * f;
    float c = cosf(a), sn = sinf(a);
    size_t base = (size_t)t * KVW_ + KVP_;
    float x1 = ckv[base + j];
    float x2 = ckv[base + 16 + j];
    kr[(size_t)t * ROPE_ + j]      = x1 * c - x2 * sn;
    kr[(size_t)t * ROPE_ + 16 + j] = x2 * c + x1 * sn;
}

// ---------------- causal flash attention (f32x2 packed) ----------------
__global__ void __launch_bounds__(256) attn_kernel(
    const float* __restrict__ Q, const float* __restrict__ kvu,
    const float* __restrict__ kr, float* __restrict__ O)
{
    int qt = blockIdx.x, h = blockIdx.y, b = blockIdx.z;
    int tid = threadIdx.x;
    int q = tid >> 2, kq = tid & 3;
    int qi = qt * 64 + q;
    int t0 = b * SS;

    __shared__ __align__(16) float ks[32][68];
    __shared__ __align__(16) float vs[32][68];

    u64t qreg[32];
    {
        const float* qp = Q + (size_t)(t0 + qi) * DD + h * DHH;
#pragma unroll
        for (int i = 0; i < 16; i++) {
            ulonglong2 v = *reinterpret_cast<const ulonglong2*>(qp + i * 4);
            qreg[2 * i] = v.x; qreg[2 * i + 1] = v.y;
        }
    }

    u64t acc2[32];
#pragma unroll
    for (int i = 0; i < 32; i++) acc2[i] = 0ull;
    float mcur = -3.0e38f, l = 0.f;

    int ntiles = 2 * qt + 2;
    for (int kt = 0; kt < ntiles; kt++) {
        int kb = kt * 32;
#pragma unroll
        for (int i = 0; i < 8; i++) {
            int idx = tid + i * 256;
            int zz = idx >> 6, d = idx & 63;
            int kg = t0 + kb + zz;
            ks[zz][d] = (d < 32) ? kvu[(size_t)kg * UKV_ + h * 96 + d]
                                 : kr[(size_t)kg * ROPE_ + (d - 32)];
            vs[zz][d] = kvu[(size_t)kg * UKV_ + h * 96 + 32 + d];
        }
        __syncthreads();

#pragma unroll 2
        for (int jj = 0; jj < 8; jj++) {
            int j = jj * 4 + kq;
            if (kb + j <= qi) {
                const ulonglong2* kp = reinterpret_cast<const ulonglong2*>(&ks[j][0]);
                u64t sa = 0ull, sb = 0ull;
#pragma unroll
                for (int i = 0; i < 16; i++) {
                    ulonglong2 kv = kp[i];
                    sa = fma2_(qreg[2 * i], kv.x, sa);
                    sb = fma2_(qreg[2 * i + 1], kv.y, sb);
                }
                float f0, f1, f2, f3;
                unpack2_(sa, f0, f1); unpack2_(sb, f2, f3);
                float s = ((f0 + f1) + (f2 + f3)) * 0.125f;
                if (s > mcur) {
                    float corr = __expf(mcur - s);
                    l *= corr;
                    u64t c2 = pack2_(corr, corr);
#pragma unroll
                    for (int i = 0; i < 32; i++) acc2[i] = mul2_(acc2[i], c2);
                    mcur = s;
                }
                float p = __expf(s - mcur);
                l += p;
                u64t p2 = pack2_(p, p);
                const ulonglong2* vp = reinterpret_cast<const ulonglong2*>(&vs[j][0]);
#pragma unroll
                for (int i = 0; i < 16; i++) {
                    ulonglong2 vv = vp[i];
                    acc2[2 * i]     = fma2_(p2, vv.x, acc2[2 * i]);
                    acc2[2 * i + 1] = fma2_(p2, vv.y, acc2[2 * i + 1]);
                }
            }
        }
        __syncthreads();
    }

    float mmax = mcur;
    mmax = fmaxf(mmax, __shfl_xor_sync(0xffffffffu, mmax, 1));
    mmax = fmaxf(mmax, __shfl_xor_sync(0xffffffffu, mmax, 2));
    float c = __expf(mcur - mmax);
    l *= c;
    l += __shfl_xor_sync(0xffffffffu, l, 1);
    l += __shfl_xor_sync(0xffffffffu, l, 2);
    u64t c2 = pack2_(c, c);
#pragma unroll
    for (int i = 0; i < 32; i++) {
        acc2[i] = mul2_(acc2[i], c2);
        acc2[i] = add2_(acc2[i], __shfl_xor_sync(0xffffffffu, acc2[i], 1));
        acc2[i] = add2_(acc2[i], __shfl_xor_sync(0xffffffffu, acc2[i], 2));
    }
    float invl = 1.f / l;
    float* op = O + (size_t)(t0 + qi) * DD + h * DHH + kq * 16;
#pragma unroll
    for (int i = 0; i < 8; i++) {
        float lo, hi;
        unpack2_(acc2[kq * 8 + i], lo, hi);
        op[2 * i] = lo * invl;
        op[2 * i + 1] = hi * invl;
    }
}

// ---------------- routing ----------------
__global__ void route_kernel(const float* __restrict__ h2,
                             const float* __restrict__ cent,
                             const float* __restrict__ bias,
                             int* __restrict__ tope, float* __restrict__ topg)
{
    int warp = (blockIdx.x * blockDim.x + threadIdx.x) >> 5;
    int lane = threadIdx.x & 31;
    if (warp >= TT) return;
    const float* hp = h2 + (size_t)warp * DD;
    float raw[EE];
    for (int e = 0; e < EE; e++) {
        const float* cp = cent + (size_t)e * DD;
        float p = 0.f;
        for (int d = lane; d < DD; d += 32) p += hp[d] * cp[d];
#pragma unroll
        for (int o = 16; o > 0; o >>= 1) p += __shfl_xor_sync(0xffffffff, p, o);
        raw[e] = p;
    }
    if (lane == 0) {
        int i0 = 0, i1 = -1;
        float b0 = -3.4e38f, b1 = -3.4e38f;
        for (int e = 0; e < EE; e++) { float v = raw[e] + bias[e]; if (v > b0) { b0 = v; i0 = e; } }
        for (int e = 0; e < EE; e++) { if (e == i0) continue; float v = raw[e] + bias[e]; if (v > b1) { b1 = v; i1 = e; } }
        float g0 = 1.f / (1.f + expf(-raw[i0]));
        float g1 = 1.f / (1.f + expf(-raw[i1]));
        float sg = g0 + g1 + 1e-9f;
        tope[warp * 2] = i0; tope[warp * 2 + 1] = i1;
        topg[warp * 2] = g0 / sg; topg[warp * 2 + 1] = g1 / sg;
    }
}

// ---------------- per-expert list build ----------------
__global__ void build_lists_kernel(const int* __restrict__ tope, const float* __restrict__ topg,
                                   int* __restrict__ eidx, float* __restrict__ egate,
                                   int* __restrict__ eslot, int* __restrict__ cnt)
{
    int e = blockIdx.x;
    int tid = threadIdx.x;
    __shared__ int c[256];
    int t0 = tid * 16;
    int lc = 0;
    for (int i = 0; i < 16; i++) {
        int t = t0 + i;
        lc += (tope[t * 2] == e) || (tope[t * 2 + 1] == e);
    }
    c[tid] = lc; __syncthreads();
    if (tid == 0) {
        int tot = 0;
        for (int i = 0; i < 256; i++) { int v = c[i]; c[i] = tot; tot += v; }
        cnt[e] = tot;
    }
    __syncthreads();
    int pos = c[tid];
    for (int i = 0; i < 16; i++) {
        int t = t0 + i;
        int slot = -1;
        if (tope[t * 2] == e) slot = 0;
        else if (tope[t * 2 + 1] == e) slot = 1;
        if (slot >= 0) {
            int p = e * TT + pos;
            eidx[p] = t;
            egate[p] = topg[t * 2 + slot];
            eslot[p] = slot;
            pos++;
        }
    }
}

__global__ void offsets_kernel(const int* __restrict__ cnt, int* __restrict__ off)
{
    if (threadIdx.x == 0) {
        int a = 0;
        for (int e = 0; e < EE; e++) { off[e] = a; a += cnt[e]; }
    }
}

// ---------------- final combine ----------------
__global__ void combine_kernel(const float* __restrict__ x2, const float* __restrict__ sh,
                               const float* __restrict__ slots, float* __restrict__ out)
{
    int i = blockIdx.x * 256 + threadIdx.x;
    if (i < TT * DD)
        out[i] = x2[i] + sh[i] + sh[TT * DD + i] + slots[i] + slots[TT * DD + i];
}

// ---------------- host launcher ----------------
#define GSMEM (4 * STGW * 4)   // 73728 bytes

static void launch_gemm(bool bt, int gz,
                        const float* A, int lda, long azs,
                        const float* B, int ldb, long bzs,
                        float* C, int ldc, long czs,
                        int M, int N, int K,
                        bool gelu, const float* addC,
                        const int* tok, const float* gate, const int* slot,
                        const int* offA, const int* cntA,
                        int amode, int cmode)
{
    dim3 grid((N + 127) / 128, (M + 127) / 128, gz);
    if (bt)
        gemm_kernel<1><<<grid, 256, GSMEM>>>(A, lda, azs, B, ldb, bzs, C, ldc, czs, M, N, K,
                                             gelu ? 1 : 0, addC, tok, gate, slot, offA, cntA,
                                             amode, cmode);
    else
        gemm_kernel<0><<<grid, 256, GSMEM>>>(A, lda, azs, B, ldb, bzs, C, ldc, czs, M, N, K,
                                             gelu ? 1 : 0, addC, tok, gate, slot, offA, cntA,
                                             amode, cmode);
}

extern "C" void kernel_launch(void* const* d_in, const int* in_sizes, int n_in,
                              void* d_out, int out_size)
{
    const float* x       = (const float*)d_in[0];
    const float* ln1_w   = (const float*)d_in[1];
    const float* ln2_w   = (const float*)d_in[2];
    const float* W_dq    = (const float*)d_in[3];
    const float* W_uq    = (const float*)d_in[4];
    const float* q_ln_w  = (const float*)d_in[5];
    const float* q_ln_b  = (const float*)d_in[6];
    const float* W_dkv   = (const float*)d_in[7];
    const float* W_ukv   = (const float*)d_in[8];
    const float* kv_ln_w = (const float*)d_in[9];
    const float* kv_ln_b = (const float*)d_in[10];
    const float* W_o     = (const float*)d_in[11];
    const float* s_fc    = (const float*)d_in[12];
    const float* s_proj  = (const float*)d_in[13];
    const float* e_fc    = (const float*)d_in[14];
    const float* e_proj  = (const float*)d_in[15];
    const float* cent    = (const float*)d_in[16];
    const float* rbias   = (const float*)d_in[17];
    float* out = (float*)d_out;

    cudaFuncSetAttribute(gemm_kernel<0>, cudaFuncAttributeMaxDynamicSharedMemorySize, GSMEM);
    cudaFuncSetAttribute(gemm_kernel<1>, cudaFuncAttributeMaxDynamicSharedMemorySize, GSMEM);

    float *h1, *cq, *q, *ckv, *kvl, *kvu, *kr, *ao, *x2, *h2, *sh, *hid, *ehid, *slots, *egate, *topg;
    int *eidx, *eslot, *cnt, *off, *tope;
    cudaGetSymbolAddress((void**)&h1, g_h1);
    cudaGetSymbolAddress((void**)&cq, g_cq);
    cudaGetSymbolAddress((void**)&q, g_q);
    cudaGetSymbolAddress((void**)&ckv, g_ckv);
    cudaGetSymbolAddress((void**)&kvl, g_kvl);
    cudaGetSymbolAddress((void**)&kvu, g_kvu);
    cudaGetSymbolAddress((void**)&kr, g_kr);
    cudaGetSymbolAddress((void**)&ao, g_ao);
    cudaGetSymbolAddress((void**)&x2, g_x2);
    cudaGetSymbolAddress((void**)&h2, g_h2);
    cudaGetSymbolAddress((void**)&sh, g_sh);
    cudaGetSymbolAddress((void**)&hid, g_hid);
    cudaGetSymbolAddress((void**)&ehid, g_ehid);
    cudaGetSymbolAddress((void**)&slots, g_slots);
    cudaGetSymbolAddress((void**)&egate, g_egate);
    cudaGetSymbolAddress((void**)&topg, g_topg);
    cudaGetSymbolAddress((void**)&eidx, g_eidx);
    cudaGetSymbolAddress((void**)&eslot, g_eslot);
    cudaGetSymbolAddress((void**)&cnt, g_cnt);
    cudaGetSymbolAddress((void**)&off, g_off);
    cudaGetSymbolAddress((void**)&tope, g_tope);

    ln_kernel<<<TT, 256>>>(x, DD, DD, h1, DD, ln1_w, nullptr);
    launch_gemm(false, 1, h1, DD, 0, W_dq, QP_, 0, cq, QP_, 0, TT, QP_, DD,
                false, nullptr, nullptr, nullptr, nullptr, nullptr, nullptr, 0, 0);
    ln_kernel<<<TT, 256>>>(cq, QP_, QP_, cq, QP_, q_ln_w, q_ln_b);
    launch_gemm(false, 1, cq, QP_, 0, W_uq, DD, 0, q, DD, 0, TT, DD, QP_,
                false, nullptr, nullptr, nullptr, nullptr, nullptr, nullptr, 0, 0);
    launch_gemm(false, 1, h1, DD, 0, W_dkv, KVW_, 0, ckv, KVW_, 0, TT, KVW_, DD,
                false, nullptr, nullptr, nullptr, nullptr, nullptr, nullptr, 0, 0);
    ln_kernel<<<TT, 256>>>(ckv, KVW_, KVP_, kvl, KVP_, kv_ln_w, kv_ln_b);
    launch_gemm(false, 1, kvl, KVP_, 0, W_ukv, UKV_, 0, kvu, UKV_, 0, TT, UKV_, KVP_,
                false, nullptr, nullptr, nullptr, nullptr, nullptr, nullptr, 0, 0);
    rope_q_kernel<<<(TT * HH * 16 + 255) / 256, 256>>>(q);
    rope_k_kernel<<<(TT * 16 + 255) / 256, 256>>>(ckv, kr);
    {
        dim3 agrid(SS / 64, HH, BB);
        attn_kernel<<<agrid, 256>>>(q, kvu, kr, ao);
    }
    launch_gemm(true, 1, ao, DD, 0, W_o, DD, 0, x2, DD, 0, TT, DD, DD,
                false, x, nullptr, nullptr, nullptr, nullptr, nullptr, 0, 0);
    ln_kernel<<<TT, 256>>>(x2, DD, DD, h2, DD, ln2_w, nullptr);

    // shared experts, batched over z=2
    launch_gemm(true, 2, h2, DD, 0, s_fc, DD, (long)FF_ * DD, hid, FF_, (long)TT * FF_,
                TT, FF_, DD, true, nullptr, nullptr, nullptr, nullptr, nullptr, nullptr, 0, 0);
    launch_gemm(true, 2, hid, FF_, (long)TT * FF_, s_proj, FF_, (long)DD * FF_, sh, DD, (long)TT * DD,
                TT, DD, FF_, false, nullptr, nullptr, nullptr, nullptr, nullptr, nullptr, 0, 0);

    // routing + lists
    route_kernel<<<TT / 4, 128>>>(h2, cent, rbias, tope, topg);
    build_lists_kernel<<<EE, 256>>>(tope, topg, eidx, egate, eslot, cnt);
    offsets_kernel<<<1, 32>>>(cnt, off);

    // routed experts, batched over z=8
    launch_gemm(true, EE, h2, DD, 0, e_fc, DD, (long)FF_ * DD, ehid, FF_, 0,
                TT, FF_, DD, true, nullptr, eidx, egate, eslot, off, cnt, 1, 1);
    launch_gemm(true, EE, ehid, FF_, 0, e_proj, FF_, (long)DD * FF_, slots, DD, 0,
                TT, DD, FF_, false, nullptr, eidx, egate, eslot, off, cnt, 2, 2);

    combine_kernel<<<(TT * DD + 255) / 256, 256>>>(x2, sh, slots, out);
}

// round 5
// speedup vs baseline: 5.0686x; 1.0266x over previous
#include <cuda_runtime.h>
#include <math.h>

// ---------------- problem constants ----------------
#define BB    4
#define SS    1024
#define TT    4096
#define DD    768
#define HH    12
#define DHH   64
#define NOPE_ 32
#define ROPE_ 32
#define QP_   384
#define KVP_  512
#define KVW_  544
#define UKV_  1152
#define EE    8
#define FF_   3072

// ---------------- scratch ----------------
__device__ __align__(256) float g_h1[TT * DD];
__device__ __align__(256) float g_cq[TT * QP_];
__device__ __align__(256) float g_q[TT * DD];
__device__ __align__(256) float g_ckv[TT * KVW_];
__device__ __align__(256) float g_kvl[TT * KVP_];
__device__ __align__(256) float g_kvu[TT * UKV_];
__device__ __align__(256) float g_kr[TT * ROPE_];
__device__ __align__(256) float g_ao[TT * DD];
__device__ __align__(256) float g_x2[TT * DD];
__device__ __align__(256) float g_h2[TT * DD];
__device__ __align__(256) float g_sh[2 * TT * DD];
__device__ __align__(256) float g_hid[2 * TT * FF_];
__device__ __align__(256) float g_ehid[2 * TT * FF_];
__device__ __align__(256) float g_slots[2 * TT * DD];
__device__ int   g_tope[TT * 2];
__device__ float g_topg[TT * 2];
__device__ int   g_eidx[EE * TT];
__device__ float g_egate[EE * TT];
__device__ int   g_eslot[EE * TT];
__device__ int   g_cnt[EE];
__device__ int   g_off[EE];

// ---------------- f32x2 packed helpers ----------------
typedef unsigned long long u64t;
__device__ __forceinline__ u64t fma2_(u64t a, u64t b, u64t c) {
    u64t d; asm("fma.rn.f32x2 %0, %1, %2, %3;" : "=l"(d) : "l"(a), "l"(b), "l"(c)); return d;
}
__device__ __forceinline__ u64t mul2_(u64t a, u64t b) {
    u64t d; asm("mul.rn.f32x2 %0, %1, %2;" : "=l"(d) : "l"(a), "l"(b)); return d;
}
__device__ __forceinline__ u64t add2_(u64t a, u64t b) {
    u64t d; asm("add.rn.f32x2 %0, %1, %2;" : "=l"(d) : "l"(a), "l"(b)); return d;
}
__device__ __forceinline__ u64t pack2_(float lo, float hi) {
    u64t d; asm("mov.b64 %0, {%1, %2};" : "=l"(d) : "f"(lo), "f"(hi)); return d;
}
__device__ __forceinline__ void unpack2_(u64t v, float& lo, float& hi) {
    asm("mov.b64 {%0, %1}, %2;" : "=f"(lo), "=f"(hi) : "l"(v));
}

// ---------------- LayerNorm ----------------
__global__ void __launch_bounds__(256) ln_kernel(
    const float* __restrict__ in, int istride, int width,
    float* __restrict__ out, int ostride,
    const float* __restrict__ w, const float* __restrict__ b)
{
    __shared__ float rowc[768];
    __shared__ float red[256];
    int r = blockIdx.x, tid = threadIdx.x;
    const float* ip = in + (size_t)r * istride;
    float s = 0.f;
    for (int i = tid; i < width; i += 256) { float v = ip[i]; rowc[i] = v; s += v; }
    red[tid] = s; __syncthreads();
    for (int st = 128; st > 0; st >>= 1) { if (tid < st) red[tid] += red[tid + st]; __syncthreads(); }
    float mean = red[0] / (float)width;
    __syncthreads();
    float s2 = 0.f;
    for (int i = tid; i < width; i += 256) { float d = rowc[i] - mean; s2 += d * d; }
    red[tid] = s2; __syncthreads();
    for (int st = 128; st > 0; st >>= 1) { if (tid < st) red[tid] += red[tid + st]; __syncthreads(); }
    float inv = rsqrtf(red[0] / (float)width + 1e-5f);
    float* op = out + (size_t)r * ostride;
    for (int i = tid; i < width; i += 256) {
        float v = (rowc[i] - mean) * inv * w[i];
        if (b) v += b[i];
        op[i] = v;
    }
}

// ---------------- TF32 tensor-core GEMM, 128x128x32, double-buffered ----------------
#define SK 36          // [row][k] stride (A always; B when BT=1)
#define SN 136         // [k][n] stride (B when BT=0)
#define STGW (128 * SK)

__device__ __forceinline__ unsigned f2tf32(float v) {
    unsigned u;
    asm("cvt.rna.tf32.f32 %0, %1;" : "=r"(u) : "f"(v));
    return u;
}

__device__ __forceinline__ void mma_tf32(float* c, const unsigned* a, const unsigned* b) {
    asm volatile("mma.sync.aligned.m16n8k8.row.col.f32.tf32.tf32.f32 "
                 "{%0,%1,%2,%3}, {%4,%5,%6,%7}, {%8,%9}, {%0,%1,%2,%3};"
                 : "+f"(c[0]), "+f"(c[1]), "+f"(c[2]), "+f"(c[3])
                 : "r"(a[0]), "r"(a[1]), "r"(a[2]), "r"(a[3]),
                   "r"(b[0]), "r"(b[1]));
}

// amode: 0 arow=m; 1 arow=tokList[z*TT+m]; 2 arow=off[z]+m
// cmode: 0 crow=m; 1 crow=off[z]+m; 2 crow=slot*TT+tok (scaled by gate)
// nsplit>0: columns [0,nsplit) use B/C, columns [nsplit,N) use B2/C2 (per-block select).
template<int BT>
__global__ void __launch_bounds__(256) gemm_kernel(
    const float* __restrict__ A, int lda, long azs,
    const float* __restrict__ B, int ldb, long bzs,
    float* __restrict__ C, int ldc, long czs,
    int M, int N, int K,
    int doGelu,
    const float* __restrict__ addC,
    const int* __restrict__ tokList, const float* __restrict__ gateList,
    const int* __restrict__ slotList,
    const int* __restrict__ offArr, const int* __restrict__ cntArr,
    int amode, int cmode,
    const float* __restrict__ B2, int ldb2, float* __restrict__ C2, int ldc2, int nsplit)
{
    int z = blockIdx.z;
    int Mreal = cntArr ? cntArr[z] : M;
    int mt = blockIdx.y * 128, nt = blockIdx.x * 128;
    if (mt >= Mreal) return;
    int offv = offArr ? offArr[z] : 0;
    int listBase = z * TT;
    A += (size_t)z * azs;
    B += (size_t)z * bzs;
    C += (size_t)z * czs;

    int Nloc = N;
    if (nsplit > 0) {
        if (nt >= nsplit) { B = B2; ldb = ldb2; C = C2; ldc = ldc2; nt -= nsplit; Nloc = N - nsplit; }
        else Nloc = nsplit;
    }

    extern __shared__ unsigned smemu[];
    unsigned* Asb = smemu;
    unsigned* Bsb = smemu + 2 * STGW;

    int tid = threadIdx.x;
    int wid = tid >> 5, lane = tid & 31;
    int wm = wid & 3, wn = wid >> 2;
    int lrow = lane >> 2;
    int lcol = lane & 3;

    float acc[2][8][4];
#pragma unroll
    for (int i = 0; i < 2; i++)
#pragma unroll
        for (int j = 0; j < 8; j++)
#pragma unroll
            for (int r = 0; r < 4; r++) acc[i][j][r] = 0.f;

    int fr = tid >> 3, ff = tid & 7;
    int arowv[4]; bool aval[4];
#pragma unroll
    for (int i = 0; i < 4; i++) {
        int gm = mt + fr + i * 32;
        aval[i] = gm < Mreal;
        int arow = 0;
        if (aval[i]) {
            if (amode == 0) arow = gm;
            else if (amode == 1) arow = tokList[listBase + gm];
            else arow = offv + gm;
        }
        arowv[i] = arow;
    }
    // B fill mapping
    bool bval[4];
    int bk0 = tid >> 5, bn0 = tid & 31;   // BT==0: k row = bk0 + i*8, n chunk = bn0*4
    if (BT == 1) {
#pragma unroll
        for (int i = 0; i < 4; i++) bval[i] = (nt + fr + i * 32) < Nloc;
    } else {
#pragma unroll
        for (int i = 0; i < 4; i++) bval[i] = (nt + bn0 * 4 + 3) < Nloc;
    }

    float4 pa[4], pb[4];
    const float4 z4 = make_float4(0.f, 0.f, 0.f, 0.f);

    auto ldgA = [&](int k0) {
#pragma unroll
        for (int i = 0; i < 4; i++)
            pa[i] = aval[i] ? *reinterpret_cast<const float4*>(A + (size_t)arowv[i] * lda + k0 + ff * 4) : z4;
    };
    auto ldgB = [&](int k0) {
        if (BT == 1) {
#pragma unroll
            for (int i = 0; i < 4; i++)
                pb[i] = bval[i] ? *reinterpret_cast<const float4*>(B + (size_t)(nt + fr + i * 32) * ldb + k0 + ff * 4) : z4;
        } else {
#pragma unroll
            for (int i = 0; i < 4; i++)
                pb[i] = bval[i] ? *reinterpret_cast<const float4*>(B + (size_t)(k0 + bk0 + i * 8) * ldb + nt + bn0 * 4) : z4;
        }
    };
    auto stsA = [&](int s) {
#pragma unroll
        for (int i = 0; i < 4; i++) {
            uint4 u = make_uint4(f2tf32(pa[i].x), f2tf32(pa[i].y), f2tf32(pa[i].z), f2tf32(pa[i].w));
            *reinterpret_cast<uint4*>(&Asb[s * STGW + (fr + i * 32) * SK + ff * 4]) = u;
        }
    };
    auto stsB = [&](int s) {
        if (BT == 1) {
#pragma unroll
            for (int i = 0; i < 4; i++) {
                uint4 u = make_uint4(f2tf32(pb[i].x), f2tf32(pb[i].y), f2tf32(pb[i].z), f2tf32(pb[i].w));
                *reinterpret_cast<uint4*>(&Bsb[s * STGW + (fr + i * 32) * SK + ff * 4]) = u;
            }
        } else {
            // [k][n] layout, stride SN: contiguous STS.128, conflict-free
#pragma unroll
            for (int i = 0; i < 4; i++) {
                uint4 u = make_uint4(f2tf32(pb[i].x), f2tf32(pb[i].y), f2tf32(pb[i].z), f2tf32(pb[i].w));
                *reinterpret_cast<uint4*>(&Bsb[s * STGW + (bk0 + i * 8) * SN + bn0 * 4]) = u;
            }
        }
    };
    auto compute_half = [&](int s, int h) {
        const unsigned* As = Asb + s * STGW;
        const unsigned* Bs = Bsb + s * STGW;
#pragma unroll
        for (int ks = 2 * h; ks < 2 * h + 2; ks++) {
            int kb = ks * 8;
            unsigned a[2][4];
#pragma unroll
            for (int m2 = 0; m2 < 2; m2++) {
                int r0 = wm * 32 + m2 * 16 + lrow;
                a[m2][0] = As[r0 * SK + kb + lcol];
                a[m2][1] = As[(r0 + 8) * SK + kb + lcol];
                a[m2][2] = As[r0 * SK + kb + 4 + lcol];
                a[m2][3] = As[(r0 + 8) * SK + kb + 4 + lcol];
            }
            unsigned b[8][2];
#pragma unroll
            for (int n2 = 0; n2 < 8; n2++) {
                int nn = wn * 64 + n2 * 8 + lrow;
                if (BT == 1) {
                    b[n2][0] = Bs[nn * SK + kb + lcol];
                    b[n2][1] = Bs[nn * SK + kb + 4 + lcol];
                } else {
                    b[n2][0] = Bs[(kb + lcol) * SN + nn];
                    b[n2][1] = Bs[(kb + 4 + lcol) * SN + nn];
                }
            }
#pragma unroll
            for (int m2 = 0; m2 < 2; m2++)
#pragma unroll
                for (int n2 = 0; n2 < 8; n2++)
                    mma_tf32(acc[m2][n2], a[m2], b[n2]);
        }
    };

    int nk = K / 32;
    ldgA(0); ldgB(0);
    stsA(0); stsB(0);
    __syncthreads();
    for (int kt = 0; kt < nk; kt++) {
        int s = kt & 1;
        bool more = (kt + 1) < nk;
        if (more) { ldgA((kt + 1) * 32); ldgB((kt + 1) * 32); }
        compute_half(s, 0);
        if (more) { stsA(s ^ 1); stsB(s ^ 1); }   // overlaps with in-flight MMAs
        compute_half(s, 1);
        __syncthreads();
    }

#pragma unroll
    for (int m2 = 0; m2 < 2; m2++) {
#pragma unroll
        for (int ri = 0; ri < 2; ri++) {
            int gm = mt + wm * 32 + m2 * 16 + lrow + ri * 8;
            if (gm >= Mreal) continue;
            int crow; float scale = 1.f;
            if (cmode == 0) crow = gm;
            else if (cmode == 1) crow = offv + gm;
            else {
                crow = slotList[listBase + gm] * TT + tokList[listBase + gm];
                scale = gateList[listBase + gm];
            }
#pragma unroll
            for (int n2 = 0; n2 < 8; n2++) {
#pragma unroll
                for (int cj = 0; cj < 2; cj++) {
                    int gn = nt + wn * 64 + n2 * 8 + lcol * 2 + cj;
                    if (gn >= Nloc) continue;
                    float v = acc[m2][n2][ri * 2 + cj];
                    if (doGelu) v = 0.5f * v * (1.f + erff(v * 0.70710678118654752f));
                    v *= scale;
                    if (addC) v += addC[(size_t)crow * ldc + gn];
                    C[(size_t)crow * ldc + gn] = v;
                }
            }
        }
    }
}

// ---------------- RoPE ----------------
__global__ void rope_q_kernel(float* __restrict__ q)
{
    int idx = blockIdx.x * blockDim.x + threadIdx.x;
    if (idx >= TT * HH * 16) return;
    int j = idx & 15;
    int h = (idx >> 4) % HH;
    int t = idx / (HH * 16);
    int s = t & (SS - 1);
    float f = powf(10000.f, -(float)j / 32.f);
    float a = (float)s * f;
    float c = cosf(a), sn = sinf(a);
    size_t base = (size_t)t * DD + h * DHH + NOPE_;
    float x1 = q[base + j];
    float x2 = q[base + 16 + j];
    q[base + j]      = x1 * c - x2 * sn;
    q[base + 16 + j] = x2 * c + x1 * sn;
}

__global__ void rope_k_kernel(const float* __restrict__ ckv, float* __restrict__ kr)
{
    int idx = blockIdx.x * blockDim.x + threadIdx.x;
    if (idx >= TT * 16) return;
    int j = idx & 15;
    int t = idx >> 4;
    int s = t & (SS - 1);
    float f = powf(10000.f, -(float)j / 32.f);
    float a = (float)s * f;
    float c = cosf(a), sn = sinf(a);
    size_t base = (size_t)t * KVW_ + KVP_;
    float x1 = ckv[base + j];
    float x2 = ckv[base + 16 + j];
    kr[(size_t)t * ROPE_ + j]      = x1 * c - x2 * sn;
    kr[(size_t)t * ROPE_ + 16 + j] = x2 * c + x1 * sn;
}

// ---------------- causal flash attention (f32x2 packed) ----------------
__global__ void __launch_bounds__(256) attn_kernel(
    const float* __restrict__ Q, const float* __restrict__ kvu,
    const float* __restrict__ kr, float* __restrict__ O)
{
    int qt = blockIdx.x, h = blockIdx.y, b = blockIdx.z;
    int tid = threadIdx.x;
    int q = tid >> 2, kq = tid & 3;
    int qi = qt * 64 + q;
    int t0 = b * SS;

    __shared__ __align__(16) float ks[32][68];
    __shared__ __align__(16) float vs[32][68];

    u64t qreg[32];
    {
        const float* qp = Q + (size_t)(t0 + qi) * DD + h * DHH;
#pragma unroll
        for (int i = 0; i < 16; i++) {
            ulonglong2 v = *reinterpret_cast<const ulonglong2*>(qp + i * 4);
            qreg[2 * i] = v.x; qreg[2 * i + 1] = v.y;
        }
    }

    u64t acc2[32];
#pragma unroll
    for (int i = 0; i < 32; i++) acc2[i] = 0ull;
    float mcur = -3.0e38f, l = 0.f;

    int ntiles = 2 * qt + 2;
    for (int kt = 0; kt < ntiles; kt++) {
        int kb = kt * 32;
#pragma unroll
        for (int i = 0; i < 8; i++) {
            int idx = tid + i * 256;
            int zz = idx >> 6, d = idx & 63;
            int kg = t0 + kb + zz;
            ks[zz][d] = (d < 32) ? kvu[(size_t)kg * UKV_ + h * 96 + d]
                                 : kr[(size_t)kg * ROPE_ + (d - 32)];
            vs[zz][d] = kvu[(size_t)kg * UKV_ + h * 96 + 32 + d];
        }
        __syncthreads();

#pragma unroll 2
        for (int jj = 0; jj < 8; jj++) {
            int j = jj * 4 + kq;
            if (kb + j <= qi) {
                const ulonglong2* kp = reinterpret_cast<const ulonglong2*>(&ks[j][0]);
                u64t sa = 0ull, sb = 0ull;
#pragma unroll
                for (int i = 0; i < 16; i++) {
                    ulonglong2 kv = kp[i];
                    sa = fma2_(qreg[2 * i], kv.x, sa);
                    sb = fma2_(qreg[2 * i + 1], kv.y, sb);
                }
                float f0, f1, f2, f3;
                unpack2_(sa, f0, f1); unpack2_(sb, f2, f3);
                float s = ((f0 + f1) + (f2 + f3)) * 0.125f;
                if (s > mcur) {
                    float corr = __expf(mcur - s);
                    l *= corr;
                    u64t c2 = pack2_(corr, corr);
#pragma unroll
                    for (int i = 0; i < 32; i++) acc2[i] = mul2_(acc2[i], c2);
                    mcur = s;
                }
                float p = __expf(s - mcur);
                l += p;
                u64t p2 = pack2_(p, p);
                const ulonglong2* vp = reinterpret_cast<const ulonglong2*>(&vs[j][0]);
#pragma unroll
                for (int i = 0; i < 16; i++) {
                    ulonglong2 vv = vp[i];
                    acc2[2 * i]     = fma2_(p2, vv.x, acc2[2 * i]);
                    acc2[2 * i + 1] = fma2_(p2, vv.y, acc2[2 * i + 1]);
                }
            }
        }
        __syncthreads();
    }

    float mmax = mcur;
    mmax = fmaxf(mmax, __shfl_xor_sync(0xffffffffu, mmax, 1));
    mmax = fmaxf(mmax, __shfl_xor_sync(0xffffffffu, mmax, 2));
    float c = __expf(mcur - mmax);
    l *= c;
    l += __shfl_xor_sync(0xffffffffu, l, 1);
    l += __shfl_xor_sync(0xffffffffu, l, 2);
    u64t c2 = pack2_(c, c);
#pragma unroll
    for (int i = 0; i < 32; i++) {
        acc2[i] = mul2_(acc2[i], c2);
        acc2[i] = add2_(acc2[i], __shfl_xor_sync(0xffffffffu, acc2[i], 1));
        acc2[i] = add2_(acc2[i], __shfl_xor_sync(0xffffffffu, acc2[i], 2));
    }
    float invl = 1.f / l;
    float* op = O + (size_t)(t0 + qi) * DD + h * DHH + kq * 16;
#pragma unroll
    for (int i = 0; i < 8; i++) {
        float lo, hi;
        unpack2_(acc2[kq * 8 + i], lo, hi);
        op[2 * i] = lo * invl;
        op[2 * i + 1] = hi * invl;
    }
}

// ---------------- routing ----------------
__global__ void route_kernel(const float* __restrict__ h2,
                             const float* __restrict__ cent,
                             const float* __restrict__ bias,
                             int* __restrict__ tope, float* __restrict__ topg)
{
    int warp = (blockIdx.x * blockDim.x + threadIdx.x) >> 5;
    int lane = threadIdx.x & 31;
    if (warp >= TT) return;
    const float* hp = h2 + (size_t)warp * DD;
    float raw[EE];
    for (int e = 0; e < EE; e++) {
        const float* cp = cent + (size_t)e * DD;
        float p = 0.f;
        for (int d = lane; d < DD; d += 32) p += hp[d] * cp[d];
#pragma unroll
        for (int o = 16; o > 0; o >>= 1) p += __shfl_xor_sync(0xffffffff, p, o);
        raw[e] = p;
    }
    if (lane == 0) {
        int i0 = 0, i1 = -1;
        float b0 = -3.4e38f, b1 = -3.4e38f;
        for (int e = 0; e < EE; e++) { float v = raw[e] + bias[e]; if (v > b0) { b0 = v; i0 = e; } }
        for (int e = 0; e < EE; e++) { if (e == i0) continue; float v = raw[e] + bias[e]; if (v > b1) { b1 = v; i1 = e; } }
        float g0 = 1.f / (1.f + expf(-raw[i0]));
        float g1 = 1.f / (1.f + expf(-raw[i1]));
        float sg = g0 + g1 + 1e-9f;
        tope[warp * 2] = i0; tope[warp * 2 + 1] = i1;
        topg[warp * 2] = g0 / sg; topg[warp * 2 + 1] = g1 / sg;
    }
}

// ---------------- per-expert list build ----------------
__global__ void build_lists_kernel(const int* __restrict__ tope, const float* __restrict__ topg,
                                   int* __restrict__ eidx, float* __restrict__ egate,
                                   int* __restrict__ eslot, int* __restrict__ cnt)
{
    int e = blockIdx.x;
    int tid = threadIdx.x;
    __shared__ int c[256];
    int t0 = tid * 16;
    int lc = 0;
    for (int i = 0; i < 16; i++) {
        int t = t0 + i;
        lc += (tope[t * 2] == e) || (tope[t * 2 + 1] == e);
    }
    c[tid] = lc; __syncthreads();
    if (tid == 0) {
        int tot = 0;
        for (int i = 0; i < 256; i++) { int v = c[i]; c[i] = tot; tot += v; }
        cnt[e] = tot;
    }
    __syncthreads();
    int pos = c[tid];
    for (int i = 0; i < 16; i++) {
        int t = t0 + i;
        int slot = -1;
        if (tope[t * 2] == e) slot = 0;
        else if (tope[t * 2 + 1] == e) slot = 1;
        if (slot >= 0) {
            int p = e * TT + pos;
            eidx[p] = t;
            egate[p] = topg[t * 2 + slot];
            eslot[p] = slot;
            pos++;
        }
    }
}

__global__ void offsets_kernel(const int* __restrict__ cnt, int* __restrict__ off)
{
    if (threadIdx.x == 0) {
        int a = 0;
        for (int e = 0; e < EE; e++) { off[e] = a; a += cnt[e]; }
    }
}

// ---------------- final combine ----------------
__global__ void combine_kernel(const float* __restrict__ x2, const float* __restrict__ sh,
                               const float* __restrict__ slots, float* __restrict__ out)
{
    int i = blockIdx.x * 256 + threadIdx.x;
    if (i < TT * DD)
        out[i] = x2[i] + sh[i] + sh[TT * DD + i] + slots[i] + slots[TT * DD + i];
}

// ---------------- host launcher ----------------
#define GSMEM (4 * STGW * 4)   // 73728 bytes

static void launch_gemm(bool bt, int gz,
                        const float* A, int lda, long azs,
                        const float* B, int ldb, long bzs,
                        float* C, int ldc, long czs,
                        int M, int N, int K,
                        bool gelu, const float* addC,
                        const int* tok, const float* gate, const int* slot,
                        const int* offA, const int* cntA,
                        int amode, int cmode,
                        const float* B2 = nullptr, int ldb2 = 0,
                        float* C2 = nullptr, int ldc2 = 0, int nsplit = 0)
{
    dim3 grid((N + 127) / 128, (M + 127) / 128, gz);
    if (bt)
        gemm_kernel<1><<<grid, 256, GSMEM>>>(A, lda, azs, B, ldb, bzs, C, ldc, czs, M, N, K,
                                             gelu ? 1 : 0, addC, tok, gate, slot, offA, cntA,
                                             amode, cmode, B2, ldb2, C2, ldc2, nsplit);
    else
        gemm_kernel<0><<<grid, 256, GSMEM>>>(A, lda, azs, B, ldb, bzs, C, ldc, czs, M, N, K,
                                             gelu ? 1 : 0, addC, tok, gate, slot, offA, cntA,
                                             amode, cmode, B2, ldb2, C2, ldc2, nsplit);
}

extern "C" void kernel_launch(void* const* d_in, const int* in_sizes, int n_in,
                              void* d_out, int out_size)
{
    const float* x       = (const float*)d_in[0];
    const float* ln1_w   = (const float*)d_in[1];
    const float* ln2_w   = (const float*)d_in[2];
    const float* W_dq    = (const float*)d_in[3];
    const float* W_uq    = (const float*)d_in[4];
    const float* q_ln_w  = (const float*)d_in[5];
    const float* q_ln_b  = (const float*)d_in[6];
    const float* W_dkv   = (const float*)d_in[7];
    const float* W_ukv   = (const float*)d_in[8];
    const float* kv_ln_w = (const float*)d_in[9];
    const float* kv_ln_b = (const float*)d_in[10];
    const float* W_o     = (const float*)d_in[11];
    const float* s_fc    = (const float*)d_in[12];
    const float* s_proj  = (const float*)d_in[13];
    const float* e_fc    = (const float*)d_in[14];
    const float* e_proj  = (const float*)d_in[15];
    const float* cent    = (const float*)d_in[16];
    const float* rbias   = (const float*)d_in[17];
    float* out = (float*)d_out;

    cudaFuncSetAttribute(gemm_kernel<0>, cudaFuncAttributeMaxDynamicSharedMemorySize, GSMEM);
    cudaFuncSetAttribute(gemm_kernel<1>, cudaFuncAttributeMaxDynamicSharedMemorySize, GSMEM);

    float *h1, *cq, *q, *ckv, *kvl, *kvu, *kr, *ao, *x2, *h2, *sh, *hid, *ehid, *slots, *egate, *topg;
    int *eidx, *eslot, *cnt, *off, *tope;
    cudaGetSymbolAddress((void**)&h1, g_h1);
    cudaGetSymbolAddress((void**)&cq, g_cq);
    cudaGetSymbolAddress((void**)&q, g_q);
    cudaGetSymbolAddress((void**)&ckv, g_ckv);
    cudaGetSymbolAddress((void**)&kvl, g_kvl);
    cudaGetSymbolAddress((void**)&kvu, g_kvu);
    cudaGetSymbolAddress((void**)&kr, g_kr);
    cudaGetSymbolAddress((void**)&ao, g_ao);
    cudaGetSymbolAddress((void**)&x2, g_x2);
    cudaGetSymbolAddress((void**)&h2, g_h2);
    cudaGetSymbolAddress((void**)&sh, g_sh);
    cudaGetSymbolAddress((void**)&hid, g_hid);
    cudaGetSymbolAddress((void**)&ehid, g_ehid);
    cudaGetSymbolAddress((void**)&slots, g_slots);
    cudaGetSymbolAddress((void**)&egate, g_egate);
    cudaGetSymbolAddress((void**)&topg, g_topg);
    cudaGetSymbolAddress((void**)&eidx, g_eidx);
    cudaGetSymbolAddress((void**)&eslot, g_eslot);
    cudaGetSymbolAddress((void**)&cnt, g_cnt);
    cudaGetSymbolAddress((void**)&off, g_off);
    cudaGetSymbolAddress((void**)&tope, g_tope);

    ln_kernel<<<TT, 256>>>(x, DD, DD, h1, DD, ln1_w, nullptr);
    // merged cq|ckv projection: N = 384 + 544 = 928, split at 384
    launch_gemm(false, 1, h1, DD, 0, W_dq, QP_, 0, cq, QP_, 0, TT, QP_ + KVW_, DD,
                false, nullptr, nullptr, nullptr, nullptr, nullptr, nullptr, 0, 0,
                W_dkv, KVW_, ckv, KVW_, QP_);
    ln_kernel<<<TT, 256>>>(cq, QP_, QP_, cq, QP_, q_ln_w, q_ln_b);
    ln_kernel<<<TT, 256>>>(ckv, KVW_, KVP_, kvl, KVP_, kv_ln_w, kv_ln_b);
    launch_gemm(false, 1, cq, QP_, 0, W_uq, DD, 0, q, DD, 0, TT, DD, QP_,
                false, nullptr, nullptr, nullptr, nullptr, nullptr, nullptr, 0, 0);
    launch_gemm(false, 1, kvl, KVP_, 0, W_ukv, UKV_, 0, kvu, UKV_, 0, TT, UKV_, KVP_,
                false, nullptr, nullptr, nullptr, nullptr, nullptr, nullptr, 0, 0);
    rope_q_kernel<<<(TT * HH * 16 + 255) / 256, 256>>>(q);
    rope_k_kernel<<<(TT * 16 + 255) / 256, 256>>>(ckv, kr);
    {
        dim3 agrid(SS / 64, HH, BB);
        attn_kernel<<<agrid, 256>>>(q, kvu, kr, ao);
    }
    launch_gemm(true, 1, ao, DD, 0, W_o, DD, 0, x2, DD, 0, TT, DD, DD,
                false, x, nullptr, nullptr, nullptr, nullptr, nullptr, 0, 0);
    ln_kernel<<<TT, 256>>>(x2, DD, DD, h2, DD, ln2_w, nullptr);

    // shared experts, batched over z=2
    launch_gemm(true, 2, h2, DD, 0, s_fc, DD, (long)FF_ * DD, hid, FF_, (long)TT * FF_,
                TT, FF_, DD, true, nullptr, nullptr, nullptr, nullptr, nullptr, nullptr, 0, 0);
    launch_gemm(true, 2, hid, FF_, (long)TT * FF_, s_proj, FF_, (long)DD * FF_, sh, DD, (long)TT * DD,
                TT, DD, FF_, false, nullptr, nullptr, nullptr, nullptr, nullptr, nullptr, 0, 0);

    // routing + lists
    route_kernel<<<TT / 4, 128>>>(h2, cent, rbias, tope, topg);
    build_lists_kernel<<<EE, 256>>>(tope, topg, eidx, egate, eslot, cnt);
    offsets_kernel<<<1, 32>>>(cnt, off);

    // routed experts, batched over z=8
    launch_gemm(true, EE, h2, DD, 0, e_fc, DD, (long)FF_ * DD, ehid, FF_, 0,
                TT, FF_, DD, true, nullptr, eidx, egate, eslot, off, cnt, 1, 1);
    launch_gemm(true, EE, ehid, FF_, 0, e_proj, FF_, (long)DD * FF_, slots, DD, 0,
                TT, DD, FF_, false, nullptr, eidx, egate, eslot, off, cnt, 2, 2);

    combine_kernel<<<(TT * DD + 255) / 256, 256>>>(x2, sh, slots, out);
}